// round 3
// baseline (speedup 1.0000x reference)
#include <cuda_runtime.h>
#include <cstdint>

// ---------------------------------------------------------------------------
// Problem constants
// ---------------------------------------------------------------------------
#define BB 32
#define DD 64
#define TT 2048
#define KK 1024
#define NN (BB * TT)              // 65536 rows
#define QELEMS (BB * DD * TT)     // 4194304
// Output (float32): [loss(1) | quantized(QELEMS) | indices(NN) | n_resurrected(1)]

#define TILE_M  128               // rows per CTA
#define CHUNK_N 128               // codewords per staged chunk
#define GRID_M  (NN / TILE_M)     // 512 CTAs
#define NCHUNK  (KK / CHUNK_N)    // 8

#define XS 68                     // smem row stride in floats (bank-conflict-free)

// Dynamic smem layout (bytes)
#define SM_X    0                 // 128 x 68 floats = 34816
#define SM_BH   34816             // 128 x 68 floats
#define SM_BL   69632             // 128 x 68 floats
#define SM_BI   104448            // 128 ints
#define SM_SI   104960            // 128 ints
#define SM_RED  105472            // 128 floats
#define SM_TOTAL 105984

__device__ float g_wnorm[KK * DD];   // normalized codebook (fp32)
__device__ float g_whi[KK * DD];     // tf32 hi part
__device__ float g_wlo[KK * DD];     // tf32 lo part
__device__ float g_partial[GRID_M];

__device__ __forceinline__ float to_tf32(float f) {
    uint32_t u;
    asm("cvt.rna.tf32.f32 %0, %1;" : "=r"(u) : "f"(f));
    return __uint_as_float(u);
}

// m16n8k8 tf32 MMA, D += A*B  (D,C same registers)
#define MMA_TF32(d, a, b0, b1)                                                \
    asm volatile("mma.sync.aligned.m16n8k8.row.col.f32.tf32.tf32.f32 "        \
                 "{%0,%1,%2,%3}, {%4,%5,%6,%7}, {%8,%9}, {%0,%1,%2,%3};"      \
                 : "+f"((d)[0]), "+f"((d)[1]), "+f"((d)[2]), "+f"((d)[3])     \
                 : "r"((a)[0]), "r"((a)[1]), "r"((a)[2]), "r"((a)[3]),        \
                   "r"(b0), "r"(b1))

// ---------------------------------------------------------------------------
// Kernel A: normalize codebook + tf32 hi/lo split. One warp per row.
// ---------------------------------------------------------------------------
__global__ void norm_weight_kernel(const float* __restrict__ w) {
    int row  = blockIdx.x * blockDim.y + threadIdx.y;
    int lane = threadIdx.x;
    float a = w[row * DD + lane];
    float b = w[row * DD + 32 + lane];
    float s = a * a + b * b;
    #pragma unroll
    for (int o = 16; o; o >>= 1) s += __shfl_xor_sync(0xFFFFFFFFu, s, o);
    float inv = 1.0f / fmaxf(sqrtf(s), 1e-12f);
    float na = a * inv, nb = b * inv;
    float ha = to_tf32(na), hb = to_tf32(nb);
    g_wnorm[row * DD + lane]      = na;
    g_wnorm[row * DD + 32 + lane] = nb;
    g_whi[row * DD + lane]        = ha;
    g_whi[row * DD + 32 + lane]   = hb;
    g_wlo[row * DD + lane]        = to_tf32(na - ha);
    g_wlo[row * DD + 32 + lane]   = to_tf32(nb - hb);
}

// ---------------------------------------------------------------------------
// Kernel B: 3-pass tf32 mma.sync dot matrix + top-2 + fp32 rescore + outputs
// ---------------------------------------------------------------------------
__global__ __launch_bounds__(256, 1)
void vq_mma_kernel(const float* __restrict__ in, float* __restrict__ out) {
    extern __shared__ char smem[];
    float* sX   = (float*)(smem + SM_X);
    float* sBH  = (float*)(smem + SM_BH);
    float* sBL  = (float*)(smem + SM_BL);
    int*   sBI  = (int*)  (smem + SM_BI);
    int*   sSI  = (int*)  (smem + SM_SI);
    float* sRED = (float*)(smem + SM_RED);

    const int tid  = threadIdx.x;
    const int wid  = tid >> 5;
    const int lane = tid & 31;
    const int g    = lane >> 2;   // groupID (0..7)
    const int tig  = lane & 3;    // thread in group

    // ---- Phase 1: load + normalize 128 rows into smem X (fp32) ----
    if (tid < TILE_M) {
        int n = blockIdx.x * TILE_M + tid;
        int b = n >> 11;
        int t = n & (TT - 1);
        const float* xp = in + (size_t)b * DD * TT + t;
        float x[DD];
        float ss = 0.0f;
        #pragma unroll
        for (int d = 0; d < DD; ++d) { float v = xp[(size_t)d * TT]; x[d] = v; ss += v * v; }
        float inv = 1.0f / fmaxf(sqrtf(ss), 1e-12f);
        #pragma unroll
        for (int d = 0; d < DD; ++d) sX[tid * XS + d] = x[d] * inv;
    }
    __syncthreads();

    // ---- Build resident A fragments (hi/lo) for this warp's 16 rows ----
    // m16n8k8 tf32 A frag: a0=(g,tig+8c) a1=(g+8,tig+8c) a2=(g,tig+4+8c) a3=(g+8,tig+4+8c)
    uint32_t AH[8][4], AL[8][4];
    {
        const int rA = wid * 16 + g;
        const int rB = rA + 8;
        #pragma unroll
        for (int c = 0; c < 8; ++c) {
            float x0 = sX[rA * XS + c * 8 + tig];
            float x1 = sX[rB * XS + c * 8 + tig];
            float x2 = sX[rA * XS + c * 8 + tig + 4];
            float x3 = sX[rB * XS + c * 8 + tig + 4];
            float h0 = to_tf32(x0), h1 = to_tf32(x1), h2 = to_tf32(x2), h3 = to_tf32(x3);
            AH[c][0] = __float_as_uint(h0);
            AH[c][1] = __float_as_uint(h1);
            AH[c][2] = __float_as_uint(h2);
            AH[c][3] = __float_as_uint(h3);
            AL[c][0] = __float_as_uint(to_tf32(x0 - h0));
            AL[c][1] = __float_as_uint(to_tf32(x1 - h1));
            AL[c][2] = __float_as_uint(to_tf32(x2 - h2));
            AL[c][3] = __float_as_uint(to_tf32(x3 - h3));
        }
    }

    const float NEGINF = -3.402823466e+38f;
    float best[2] = {NEGINF, NEGINF}, sec[2] = {NEGINF, NEGINF};
    int   bidx[2] = {0, 0},           sidx[2] = {0, 0};

    for (int nt = 0; nt < NCHUNK; ++nt) {
        __syncthreads();   // previous chunk's B reads complete
        // ---- Stage B chunk: 128 codewords x 64 dims, hi & lo ----
        {
            int row  = tid >> 1;
            int half = tid & 1;
            const float4* srcH = (const float4*)(g_whi + (size_t)(nt * CHUNK_N + row) * DD + half * 32);
            const float4* srcL = (const float4*)(g_wlo + (size_t)(nt * CHUNK_N + row) * DD + half * 32);
            float4* dh = (float4*)(sBH + row * XS + half * 32);
            float4* dl = (float4*)(sBL + row * XS + half * 32);
            #pragma unroll
            for (int i = 0; i < 8; ++i) { dh[i] = srcH[i]; dl[i] = srcL[i]; }
        }
        __syncthreads();

        // ---- 8 n8-tile pairs; 6 independent accumulator chains each ----
        #pragma unroll 1
        for (int p = 0; p < 8; ++p) {
            const int n0 = p * 16;
            float aHH0[4] = {0,0,0,0}, aHL0[4] = {0,0,0,0}, aLH0[4] = {0,0,0,0};
            float aHH1[4] = {0,0,0,0}, aHL1[4] = {0,0,0,0}, aLH1[4] = {0,0,0,0};
            #pragma unroll
            for (int c = 0; c < 8; ++c) {
                const int k = c * 8 + tig;
                // B frag: b0=(k=tig+8c, n=g), b1=(k=tig+4+8c, n=g)
                uint32_t bh00 = __float_as_uint(sBH[(n0 + g) * XS + k]);
                uint32_t bh01 = __float_as_uint(sBH[(n0 + g) * XS + k + 4]);
                uint32_t bl00 = __float_as_uint(sBL[(n0 + g) * XS + k]);
                uint32_t bl01 = __float_as_uint(sBL[(n0 + g) * XS + k + 4]);
                uint32_t bh10 = __float_as_uint(sBH[(n0 + 8 + g) * XS + k]);
                uint32_t bh11 = __float_as_uint(sBH[(n0 + 8 + g) * XS + k + 4]);
                uint32_t bl10 = __float_as_uint(sBL[(n0 + 8 + g) * XS + k]);
                uint32_t bl11 = __float_as_uint(sBL[(n0 + 8 + g) * XS + k + 4]);
                MMA_TF32(aHH0, AH[c], bh00, bh01);
                MMA_TF32(aHL0, AH[c], bl00, bl01);
                MMA_TF32(aLH0, AL[c], bh00, bh01);
                MMA_TF32(aHH1, AH[c], bh10, bh11);
                MMA_TF32(aHL1, AH[c], bl10, bl11);
                MMA_TF32(aLH1, AL[c], bh10, bh11);
            }
            // combine passes + top-2 update
            // c frag: e0=(g, 2*tig) e1=(g, 2*tig+1) e2=(g+8, 2*tig) e3=(g+8, 2*tig+1)
            #pragma unroll
            for (int e = 0; e < 4; ++e) {
                const int r = e >> 1;
                float v0 = aHH0[e] + aHL0[e] + aLH0[e];
                int   i0 = nt * CHUNK_N + n0 + 2 * tig + (e & 1);
                if (v0 > best[r]) { sec[r] = best[r]; sidx[r] = bidx[r]; best[r] = v0; bidx[r] = i0; }
                else if (v0 > sec[r]) { sec[r] = v0; sidx[r] = i0; }
                float v1 = aHH1[e] + aHL1[e] + aLH1[e];
                int   i1 = i0 + 8;
                if (v1 > best[r]) { sec[r] = best[r]; sidx[r] = bidx[r]; best[r] = v1; bidx[r] = i1; }
                else if (v1 > sec[r]) { sec[r] = v1; sidx[r] = i1; }
            }
        }
    }

    // ---- Merge top-2 across the 4 lanes of each group (butterfly) ----
    #pragma unroll
    for (int off = 1; off <= 2; off <<= 1) {
        #pragma unroll
        for (int r = 0; r < 2; ++r) {
            float vb = __shfl_xor_sync(0xFFFFFFFFu, best[r], off);
            int   ib = __shfl_xor_sync(0xFFFFFFFFu, bidx[r], off);
            float vs = __shfl_xor_sync(0xFFFFFFFFu, sec[r],  off);
            int   is = __shfl_xor_sync(0xFFFFFFFFu, sidx[r], off);
            if (vb > best[r] || (vb == best[r] && ib < bidx[r])) {
                if (best[r] > vs || (best[r] == vs && bidx[r] < is)) { sec[r] = best[r]; sidx[r] = bidx[r]; }
                else                                                 { sec[r] = vs;      sidx[r] = is; }
                best[r] = vb; bidx[r] = ib;
            } else if (vb > sec[r] || (vb == sec[r] && ib < sidx[r])) {
                sec[r] = vb; sidx[r] = ib;
            }
        }
    }
    if (tig == 0) {
        sBI[wid * 16 + g]     = bidx[0];
        sSI[wid * 16 + g]     = sidx[0];
        sBI[wid * 16 + g + 8] = bidx[1];
        sSI[wid * 16 + g + 8] = sidx[1];
    }
    __syncthreads();

    // ---- Epilogue: fp32 rescore of top-2, gather, outputs ----
    if (tid < TILE_M) {
        int n = blockIdx.x * TILE_M + tid;
        int b = n >> 11;
        int t = n & (TT - 1);
        int i1 = sBI[tid], i2 = sSI[tid];
        const float* w1 = g_wnorm + (size_t)i1 * DD;
        const float* w2 = g_wnorm + (size_t)i2 * DD;
        const float* xr = sX + tid * XS;
        float d1 = 0.0f, d2 = 0.0f;
        #pragma unroll
        for (int d = 0; d < DD; ++d) { d1 += xr[d] * w1[d]; d2 += xr[d] * w2[d]; }
        int fin = i1;
        const float* wf = w1;
        if (d2 > d1 || (d2 == d1 && i2 < i1)) { fin = i2; wf = w2; }

        float* qp = out + 1 + (size_t)b * DD * TT + t;
        float err = 0.0f;
        #pragma unroll
        for (int d = 0; d < DD; ++d) {
            float q = wf[d];
            qp[(size_t)d * TT] = q;
            float e = q - xr[d];
            err += e * e;
        }
        out[1 + QELEMS + n] = (float)fin;
        sRED[tid] = err;
    }
    __syncthreads();
    #pragma unroll
    for (int s = 64; s > 0; s >>= 1) {
        if (tid < s) sRED[tid] += sRED[tid + s];
        __syncthreads();
    }
    if (tid == 0) g_partial[blockIdx.x] = sRED[0];
}

// ---------------------------------------------------------------------------
// Kernel C: final loss reduce. e_latent == q_latent in value -> 1.25 * mean.
// ---------------------------------------------------------------------------
__global__ void finalize_kernel(float* __restrict__ out, int out_size) {
    __shared__ float red[GRID_M];
    red[threadIdx.x] = g_partial[threadIdx.x];
    __syncthreads();
    #pragma unroll
    for (int s = GRID_M / 2; s > 0; s >>= 1) {
        if (threadIdx.x < s) red[threadIdx.x] += red[threadIdx.x + s];
        __syncthreads();
    }
    if (threadIdx.x == 0) {
        out[0] = 1.25f * red[0] / (float)QELEMS;
        out[out_size - 1] = 0.0f;
    }
}

// ---------------------------------------------------------------------------
extern "C" void kernel_launch(void* const* d_in, const int* in_sizes, int n_in,
                              void* d_out, int out_size) {
    const float* in = (const float*)d_in[0];   // [B, D, T] float32
    const float* w  = (const float*)d_in[1];   // [K, D]    float32
    float* out = (float*)d_out;

    cudaFuncSetAttribute(vq_mma_kernel, cudaFuncAttributeMaxDynamicSharedMemorySize, SM_TOTAL);

    norm_weight_kernel<<<KK / 8, dim3(32, 8)>>>(w);
    vq_mma_kernel<<<GRID_M, 256, SM_TOTAL>>>(in, out);
    finalize_kernel<<<1, GRID_M>>>(out, out_size);
}

// round 4
// speedup vs baseline: 1.5399x; 1.5399x over previous
#include <cuda_runtime.h>
#include <cuda_fp16.h>
#include <cstdint>

// ---------------------------------------------------------------------------
// Problem constants
// ---------------------------------------------------------------------------
#define BB 32
#define DD 64
#define TT 2048
#define KK 1024
#define NN (BB * TT)              // 65536 rows
#define QELEMS (BB * DD * TT)     // 4194304
// Output (float32): [loss(1) | quantized(QELEMS) | indices(NN) | n_resurrected(1)]

#define TILE_M  128               // rows per CTA
#define CHUNK_N 128               // codewords per staged chunk
#define GRID_M  (NN / TILE_M)     // 512 CTAs
#define NCHUNK  (KK / CHUNK_N)    // 8

#define XS 68                     // sX row stride (floats)
#define BS 72                     // sB row stride (halves) -> conflict-free frags

// Dynamic smem layout (bytes)
#define SM_X    0                 // 128 x 68 floats  = 34816
#define SM_B    34816             // 128 x 72 halves  = 18432
#define SM_BI   53248             // 128 ints
#define SM_RED  53760             // 128 floats
#define SM_TOTAL 54272

__device__ float  g_wnorm[KK * DD];   // normalized codebook (fp32, exact rescore)
__device__ __half g_wh[KK * DD];      // normalized codebook (fp16, mma operand)
__device__ float  g_partial[GRID_M];

// m16n8k16 fp16 MMA, fp32 accum, D += A*B
#define MMA_F16(d, a, b0, b1)                                                 \
    asm volatile("mma.sync.aligned.m16n8k16.row.col.f32.f16.f16.f32 "         \
                 "{%0,%1,%2,%3}, {%4,%5,%6,%7}, {%8,%9}, {%0,%1,%2,%3};"      \
                 : "+f"((d)[0]), "+f"((d)[1]), "+f"((d)[2]), "+f"((d)[3])     \
                 : "r"((a)[0]), "r"((a)[1]), "r"((a)[2]), "r"((a)[3]),        \
                   "r"(b0), "r"(b1))

__device__ __forceinline__ uint32_t pack_h2(float a, float b) {
    __half2 h = __floats2half2_rn(a, b);
    return *(uint32_t*)&h;
}

// ---------------------------------------------------------------------------
// Kernel A: normalize codebook -> fp32 exact + fp16 operand. One warp per row.
// ---------------------------------------------------------------------------
__global__ void norm_weight_kernel(const float* __restrict__ w) {
    int row  = blockIdx.x * blockDim.y + threadIdx.y;
    int lane = threadIdx.x;
    float a = w[row * DD + lane];
    float b = w[row * DD + 32 + lane];
    float s = a * a + b * b;
    #pragma unroll
    for (int o = 16; o; o >>= 1) s += __shfl_xor_sync(0xFFFFFFFFu, s, o);
    float inv = 1.0f / fmaxf(sqrtf(s), 1e-12f);
    float na = a * inv, nb = b * inv;
    g_wnorm[row * DD + lane]      = na;
    g_wnorm[row * DD + 32 + lane] = nb;
    g_wh[row * DD + lane]         = __float2half_rn(na);
    g_wh[row * DD + 32 + lane]    = __float2half_rn(nb);
}

// ---------------------------------------------------------------------------
// Kernel B: 1-pass fp16 mma dot matrix + per-lane top-2 + fp32 rescore
// ---------------------------------------------------------------------------
__global__ __launch_bounds__(256, 2)
void vq_mma_kernel(const float* __restrict__ in, float* __restrict__ out) {
    extern __shared__ char smem[];
    float*    sX   = (float*)(smem + SM_X);
    __half*   sB   = (__half*)(smem + SM_B);
    uint32_t* sB32 = (uint32_t*)(smem + SM_B);
    int*      sBI  = (int*)(smem + SM_BI);
    float*    sRED = (float*)(smem + SM_RED);

    const int tid  = threadIdx.x;
    const int wid  = tid >> 5;
    const int lane = tid & 31;
    const int g    = lane >> 2;   // groupID (0..7)
    const int tig  = lane & 3;    // thread in group

    // ---- Phase 1: load + normalize 128 rows into smem X (fp32) ----
    if (tid < TILE_M) {
        int n = blockIdx.x * TILE_M + tid;
        int b = n >> 11;
        int t = n & (TT - 1);
        const float* xp = in + (size_t)b * DD * TT + t;
        float x[DD];
        float ss = 0.0f;
        #pragma unroll
        for (int d = 0; d < DD; ++d) { float v = xp[(size_t)d * TT]; x[d] = v; ss += v * v; }
        float inv = 1.0f / fmaxf(sqrtf(ss), 1e-12f);
        #pragma unroll
        for (int d = 0; d < DD; ++d) sX[tid * XS + d] = x[d] * inv;
    }
    __syncthreads();

    // ---- Resident A fragments (fp16) for this warp's 16 rows ----
    // m16n8k16 A frag (row-major): a0={(g,2t),(g,2t+1)} a1={(g+8,..)}
    //                              a2={(g,2t+8),(g,2t+9)} a3={(g+8,..)}
    const int rA = wid * 16 + g;
    const int rB = rA + 8;
    uint32_t A[4][4];
    #pragma unroll
    for (int c = 0; c < 4; ++c) {
        int k0 = c * 16 + 2 * tig;
        A[c][0] = pack_h2(sX[rA * XS + k0],     sX[rA * XS + k0 + 1]);
        A[c][1] = pack_h2(sX[rB * XS + k0],     sX[rB * XS + k0 + 1]);
        A[c][2] = pack_h2(sX[rA * XS + k0 + 8], sX[rA * XS + k0 + 9]);
        A[c][3] = pack_h2(sX[rB * XS + k0 + 8], sX[rB * XS + k0 + 9]);
    }

    const float NEGINF = -3.402823466e+38f;
    float bv0[2] = {NEGINF, NEGINF}, bv1[2] = {NEGINF, NEGINF};
    int   bi0[2] = {0, 0},           bi1[2] = {0, 0};

    for (int nt = 0; nt < NCHUNK; ++nt) {
        __syncthreads();   // previous chunk's B reads complete
        // ---- Stage B chunk: 128 codewords x 64 halves (float4 copies) ----
        {
            const float4* src = (const float4*)(g_wh + (size_t)nt * CHUNK_N * DD);
            #pragma unroll
            for (int it = 0; it < 4; ++it) {
                int gi  = tid + it * 256;      // [0,1024) float4 index
                int row = gi >> 3;
                int j   = gi & 7;
                *(float4*)(sB + row * BS + j * 8) = src[gi];
            }
        }
        __syncthreads();

        // ---- 8 n16-tiles: 2 independent accumulator chains each ----
        #pragma unroll 1
        for (int p = 0; p < 8; ++p) {
            const int n0 = p * 16;
            float acc0[4] = {0, 0, 0, 0}, acc1[4] = {0, 0, 0, 0};
            #pragma unroll
            for (int c = 0; c < 4; ++c) {
                // B frag (col-major): b0={(2t,n),(2t+1,n)} b1={(2t+8,n),(2t+9,n)}
                int o0 = (n0 + g) * (BS / 2) + c * 8 + tig;
                uint32_t b00 = sB32[o0];
                uint32_t b01 = sB32[o0 + 4];
                uint32_t b10 = sB32[o0 + 8 * (BS / 2)];
                uint32_t b11 = sB32[o0 + 8 * (BS / 2) + 4];
                MMA_F16(acc0, A[c], b00, b01);
                MMA_F16(acc1, A[c], b10, b11);
            }
            // top-2 update (per-lane, per row). Scan order ascending in index,
            // strict '>' keeps the smallest index among equals.
            #pragma unroll
            for (int e = 0; e < 4; ++e) {
                const int r = e >> 1;
                float v0 = acc0[e];
                int   i0 = nt * CHUNK_N + n0 + 2 * tig + (e & 1);
                if (v0 > bv0[r])      { bv1[r] = bv0[r]; bi1[r] = bi0[r]; bv0[r] = v0; bi0[r] = i0; }
                else if (v0 > bv1[r]) { bv1[r] = v0; bi1[r] = i0; }
                float v1 = acc1[e];
                int   i1 = i0 + 8;
                if (v1 > bv0[r])      { bv1[r] = bv0[r]; bi1[r] = bi0[r]; bv0[r] = v1; bi0[r] = i1; }
                else if (v1 > bv1[r]) { bv1[r] = v1; bi1[r] = i1; }
            }
        }
    }

    // ---- Exact fp32 rescore of this lane's 2 candidates per row ----
    #pragma unroll
    for (int r = 0; r < 2; ++r) {
        const int row = (r == 0) ? rA : rB;
        const float* xr = sX + row * XS;
        const float* w1 = g_wnorm + (size_t)bi0[r] * DD;
        const float* w2 = g_wnorm + (size_t)bi1[r] * DD;
        float d1 = 0.0f, d2 = 0.0f;
        #pragma unroll
        for (int d = 0; d < DD; ++d) { d1 += xr[d] * w1[d]; d2 += xr[d] * w2[d]; }
        float v = d1; int idx = bi0[r];
        if (d2 > v || (d2 == v && bi1[r] < idx)) { v = d2; idx = bi1[r]; }
        // merge exact winners across the 4 lanes of the group
        #pragma unroll
        for (int off = 1; off <= 2; off <<= 1) {
            float vo = __shfl_xor_sync(0xFFFFFFFFu, v, off);
            int   io = __shfl_xor_sync(0xFFFFFFFFu, idx, off);
            if (vo > v || (vo == v && io < idx)) { v = vo; idx = io; }
        }
        if (tig == 0) sBI[row] = idx;
    }
    __syncthreads();

    // ---- Epilogue: gather codeword, write quantized/index, loss partial ----
    if (tid < TILE_M) {
        int n = blockIdx.x * TILE_M + tid;
        int b = n >> 11;
        int t = n & (TT - 1);
        int fin = sBI[tid];
        const float* wf = g_wnorm + (size_t)fin * DD;
        const float* xr = sX + tid * XS;
        float* qp = out + 1 + (size_t)b * DD * TT + t;
        float err = 0.0f;
        #pragma unroll
        for (int d = 0; d < DD; ++d) {
            float q = wf[d];
            qp[(size_t)d * TT] = q;
            float e = q - xr[d];
            err += e * e;
        }
        out[1 + QELEMS + n] = (float)fin;
        sRED[tid] = err;
    }
    __syncthreads();
    #pragma unroll
    for (int s = 64; s > 0; s >>= 1) {
        if (tid < s) sRED[tid] += sRED[tid + s];
        __syncthreads();
    }
    if (tid == 0) g_partial[blockIdx.x] = sRED[0];
}

// ---------------------------------------------------------------------------
// Kernel C: final loss reduce. e_latent == q_latent in value -> 1.25 * mean.
// ---------------------------------------------------------------------------
__global__ void finalize_kernel(float* __restrict__ out, int out_size) {
    __shared__ float red[GRID_M];
    red[threadIdx.x] = g_partial[threadIdx.x];
    __syncthreads();
    #pragma unroll
    for (int s = GRID_M / 2; s > 0; s >>= 1) {
        if (threadIdx.x < s) red[threadIdx.x] += red[threadIdx.x + s];
        __syncthreads();
    }
    if (threadIdx.x == 0) {
        out[0] = 1.25f * red[0] / (float)QELEMS;
        out[out_size - 1] = 0.0f;
    }
}

// ---------------------------------------------------------------------------
extern "C" void kernel_launch(void* const* d_in, const int* in_sizes, int n_in,
                              void* d_out, int out_size) {
    const float* in = (const float*)d_in[0];   // [B, D, T] float32
    const float* w  = (const float*)d_in[1];   // [K, D]    float32
    float* out = (float*)d_out;

    cudaFuncSetAttribute(vq_mma_kernel, cudaFuncAttributeMaxDynamicSharedMemorySize, SM_TOTAL);

    norm_weight_kernel<<<KK / 8, dim3(32, 8)>>>(w);
    vq_mma_kernel<<<GRID_M, 256, SM_TOTAL>>>(in, out);
    finalize_kernel<<<1, GRID_M>>>(out, out_size);
}

// round 5
// speedup vs baseline: 1.5949x; 1.0357x over previous
#include <cuda_runtime.h>
#include <cuda_fp16.h>
#include <cstdint>

// ---------------------------------------------------------------------------
// Problem constants
// ---------------------------------------------------------------------------
#define BB 32
#define DD 64
#define TT 2048
#define KK 1024
#define NN (BB * TT)              // 65536 rows
#define QELEMS (BB * DD * TT)     // 4194304
// Output (float32): [loss(1) | quantized(QELEMS) | indices(NN) | n_resurrected(1)]

#define TILE_M  128               // rows per CTA
#define CHUNK_N 128               // codewords per staged chunk
#define GRID_M  (NN / TILE_M)     // 512 CTAs
#define NCHUNK  (KK / CHUNK_N)    // 8

#define XS 68                     // sX row stride (floats)
#define BS 72                     // sB row stride (halves) -> conflict-free frags
#define B_BUF_HALVES (CHUNK_N * BS)          // 9216 halves = 18432 B

// Dynamic smem layout (bytes)
#define SM_X    0                 // 128 x 68 floats  = 34816
#define SM_B    34816             // 2 x (128 x 72 halves) = 36864 (ping-pong)
#define SM_BI   71680             // 128 ints
#define SM_RED  72192             // 128 floats
#define SM_TOTAL 72704

__device__ float  g_wnorm[KK * DD];   // normalized codebook (fp32, exact rescore)
__device__ __half g_wh[KK * DD];      // normalized codebook (fp16, mma operand)
__device__ float  g_partial[GRID_M];

// m16n8k16 fp16 MMA, fp32 accum, D += A*B
#define MMA_F16(d, a, b0, b1)                                                 \
    asm volatile("mma.sync.aligned.m16n8k16.row.col.f32.f16.f16.f32 "         \
                 "{%0,%1,%2,%3}, {%4,%5,%6,%7}, {%8,%9}, {%0,%1,%2,%3};"      \
                 : "+f"((d)[0]), "+f"((d)[1]), "+f"((d)[2]), "+f"((d)[3])     \
                 : "r"((a)[0]), "r"((a)[1]), "r"((a)[2]), "r"((a)[3]),        \
                   "r"(b0), "r"(b1))

#define CP_ASYNC_16(dst_u32, src_ptr) \
    asm volatile("cp.async.ca.shared.global [%0], [%1], 16;" \
                 :: "r"(dst_u32), "l"(src_ptr) : "memory")
#define CP_ASYNC_COMMIT() asm volatile("cp.async.commit_group;" ::: "memory")
#define CP_ASYNC_WAIT(n)  asm volatile("cp.async.wait_group %0;" :: "n"(n) : "memory")

__device__ __forceinline__ uint32_t smem_to_u32(const void* p) {
    uint32_t a;
    asm("{ .reg .u64 t; cvta.to.shared.u64 t, %1; cvt.u32.u64 %0, t; }" : "=r"(a) : "l"(p));
    return a;
}
__device__ __forceinline__ uint32_t pack_h2(float a, float b) {
    __half2 h = __floats2half2_rn(a, b);
    return *(uint32_t*)&h;
}

// ---------------------------------------------------------------------------
// Kernel A: normalize codebook -> fp32 exact + fp16 operand. One warp per row.
// ---------------------------------------------------------------------------
__global__ void norm_weight_kernel(const float* __restrict__ w) {
    int row  = blockIdx.x * blockDim.y + threadIdx.y;
    int lane = threadIdx.x;
    float a = w[row * DD + lane];
    float b = w[row * DD + 32 + lane];
    float s = a * a + b * b;
    #pragma unroll
    for (int o = 16; o; o >>= 1) s += __shfl_xor_sync(0xFFFFFFFFu, s, o);
    float inv = 1.0f / fmaxf(sqrtf(s), 1e-12f);
    float na = a * inv, nb = b * inv;
    g_wnorm[row * DD + lane]      = na;
    g_wnorm[row * DD + 32 + lane] = nb;
    g_wh[row * DD + lane]         = __float2half_rn(na);
    g_wh[row * DD + 32 + lane]    = __float2half_rn(nb);
}

// ---------------------------------------------------------------------------
// Kernel B: fp16 mma dot matrix, cp.async double-buffered, tile-pair pipelined
// ---------------------------------------------------------------------------
__global__ __launch_bounds__(256, 2)
void vq_mma_kernel(const float* __restrict__ in, float* __restrict__ out) {
    extern __shared__ char smem[];
    float*    sX   = (float*)(smem + SM_X);
    __half*   sB   = (__half*)(smem + SM_B);
    int*      sBI  = (int*)(smem + SM_BI);
    float*    sRED = (float*)(smem + SM_RED);

    const int tid  = threadIdx.x;
    const int wid  = tid >> 5;
    const int lane = tid & 31;
    const int g    = lane >> 2;   // groupID (0..7)
    const int tig  = lane & 3;    // thread in group

    const uint32_t sB_u32 = smem_to_u32(sB);

    // ---- Kick off chunk-0 staging immediately (overlaps with phase 1) ----
    {
        const char* src = (const char*)g_wh;   // chunk 0 base
        #pragma unroll
        for (int it = 0; it < 4; ++it) {
            int gi  = tid + it * 256;          // [0,1024) 16B units
            int row = gi >> 3;
            int j   = gi & 7;
            CP_ASYNC_16(sB_u32 + (uint32_t)(row * BS + j * 8) * 2, src + gi * 16);
        }
        CP_ASYNC_COMMIT();
    }

    // ---- Phase 1: load + normalize 128 rows into smem X (fp32) ----
    if (tid < TILE_M) {
        int n = blockIdx.x * TILE_M + tid;
        int b = n >> 11;
        int t = n & (TT - 1);
        const float* xp = in + (size_t)b * DD * TT + t;
        float x[DD];
        float ss = 0.0f;
        #pragma unroll
        for (int d = 0; d < DD; ++d) { float v = xp[(size_t)d * TT]; x[d] = v; ss += v * v; }
        float inv = 1.0f / fmaxf(sqrtf(ss), 1e-12f);
        #pragma unroll
        for (int d = 0; d < DD; ++d) sX[tid * XS + d] = x[d] * inv;
    }
    __syncthreads();

    // ---- Resident A fragments (fp16) for this warp's 16 rows ----
    const int rA = wid * 16 + g;
    const int rB = rA + 8;
    uint32_t A[4][4];
    #pragma unroll
    for (int c = 0; c < 4; ++c) {
        int k0 = c * 16 + 2 * tig;
        A[c][0] = pack_h2(sX[rA * XS + k0],     sX[rA * XS + k0 + 1]);
        A[c][1] = pack_h2(sX[rB * XS + k0],     sX[rB * XS + k0 + 1]);
        A[c][2] = pack_h2(sX[rA * XS + k0 + 8], sX[rA * XS + k0 + 9]);
        A[c][3] = pack_h2(sX[rB * XS + k0 + 8], sX[rB * XS + k0 + 9]);
    }

    const float NEGINF = -3.402823466e+38f;
    float bv0[2] = {NEGINF, NEGINF}, bv1[2] = {NEGINF, NEGINF};
    int   bi0[2] = {0, 0},           bi1[2] = {0, 0};

    for (int nt = 0; nt < NCHUNK; ++nt) {
        // ---- Issue staging for chunk nt+1 into the other buffer ----
        if (nt < NCHUNK - 1) {
            const char* src = (const char*)(g_wh + (size_t)(nt + 1) * CHUNK_N * DD);
            uint32_t dstb = sB_u32 + (uint32_t)(((nt + 1) & 1) * B_BUF_HALVES) * 2;
            #pragma unroll
            for (int it = 0; it < 4; ++it) {
                int gi  = tid + it * 256;
                int row = gi >> 3;
                int j   = gi & 7;
                CP_ASYNC_16(dstb + (uint32_t)(row * BS + j * 8) * 2, src + gi * 16);
            }
            CP_ASYNC_COMMIT();
            CP_ASYNC_WAIT(1);            // chunk nt resident; nt+1 in flight
        } else {
            CP_ASYNC_WAIT(0);
        }
        __syncthreads();

        const uint32_t* sB32 = (const uint32_t*)(sB + (nt & 1) * B_BUF_HALVES);
        const int base_idx = nt * CHUNK_N + 2 * tig;

        // ---- 4 tile-pairs: load all 32 B frags, then 16 MMAs, then select ----
        #pragma unroll
        for (int pp = 0; pp < 4; ++pp) {
            const int n0 = pp * 32;          // tiles n0 and n0+16
            // B fragment loads for both tiles (32 independent LDS)
            uint32_t b[2][2][4][2];          // [tile][chain][c][half]
            #pragma unroll
            for (int c = 0; c < 4; ++c) {
                int o = (n0 + g) * (BS / 2) + c * 8 + tig;
                b[0][0][c][0] = sB32[o];
                b[0][0][c][1] = sB32[o + 4];
                b[0][1][c][0] = sB32[o + 8 * (BS / 2)];
                b[0][1][c][1] = sB32[o + 8 * (BS / 2) + 4];
                b[1][0][c][0] = sB32[o + 16 * (BS / 2)];
                b[1][0][c][1] = sB32[o + 16 * (BS / 2) + 4];
                b[1][1][c][0] = sB32[o + 24 * (BS / 2)];
                b[1][1][c][1] = sB32[o + 24 * (BS / 2) + 4];
            }
            // 4 independent accumulator chains
            float acc[2][2][4];
            #pragma unroll
            for (int q = 0; q < 2; ++q)
                #pragma unroll
                for (int h = 0; h < 2; ++h)
                    #pragma unroll
                    for (int e = 0; e < 4; ++e) acc[q][h][e] = 0.0f;
            #pragma unroll
            for (int c = 0; c < 4; ++c) {
                MMA_F16(acc[0][0], A[c], b[0][0][c][0], b[0][0][c][1]);
                MMA_F16(acc[0][1], A[c], b[0][1][c][0], b[0][1][c][1]);
                MMA_F16(acc[1][0], A[c], b[1][0][c][0], b[1][0][c][1]);
                MMA_F16(acc[1][1], A[c], b[1][1][c][0], b[1][1][c][1]);
            }
            // top-2 update (ascending index order; strict '>' keeps first index)
            #pragma unroll
            for (int q = 0; q < 2; ++q) {
                #pragma unroll
                for (int h = 0; h < 2; ++h) {
                    const int ib = base_idx + n0 + q * 16 + h * 8;
                    #pragma unroll
                    for (int e = 0; e < 4; ++e) {
                        const int r = e >> 1;
                        float v = acc[q][h][e];
                        int   i = ib + (e & 1);
                        if (v > bv0[r])      { bv1[r] = bv0[r]; bi1[r] = bi0[r]; bv0[r] = v; bi0[r] = i; }
                        else if (v > bv1[r]) { bv1[r] = v; bi1[r] = i; }
                    }
                }
            }
        }
        __syncthreads();   // all warps done reading buf[nt&1] before it is refilled
    }

    // ---- Exact fp32 rescore of this lane's 2 candidates per row ----
    #pragma unroll
    for (int r = 0; r < 2; ++r) {
        const int row = (r == 0) ? rA : rB;
        const float* xr = sX + row * XS;
        const float* w1 = g_wnorm + (size_t)bi0[r] * DD;
        const float* w2 = g_wnorm + (size_t)bi1[r] * DD;
        float d1 = 0.0f, d2 = 0.0f;
        #pragma unroll
        for (int d = 0; d < DD; ++d) { d1 += xr[d] * w1[d]; d2 += xr[d] * w2[d]; }
        float v = d1; int idx = bi0[r];
        if (d2 > v || (d2 == v && bi1[r] < idx)) { v = d2; idx = bi1[r]; }
        // merge exact winners across the 4 lanes of the group
        #pragma unroll
        for (int off = 1; off <= 2; off <<= 1) {
            float vo = __shfl_xor_sync(0xFFFFFFFFu, v, off);
            int   io = __shfl_xor_sync(0xFFFFFFFFu, idx, off);
            if (vo > v || (vo == v && io < idx)) { v = vo; idx = io; }
        }
        if (tig == 0) sBI[row] = idx;
    }
    __syncthreads();

    // ---- Epilogue: gather codeword, write quantized/index, loss partial ----
    if (tid < TILE_M) {
        int n = blockIdx.x * TILE_M + tid;
        int b = n >> 11;
        int t = n & (TT - 1);
        int fin = sBI[tid];
        const float* wf = g_wnorm + (size_t)fin * DD;
        const float* xr = sX + tid * XS;
        float* qp = out + 1 + (size_t)b * DD * TT + t;
        float err = 0.0f;
        #pragma unroll
        for (int d = 0; d < DD; ++d) {
            float q = wf[d];
            qp[(size_t)d * TT] = q;
            float e = q - xr[d];
            err += e * e;
        }
        out[1 + QELEMS + n] = (float)fin;
        sRED[tid] = err;
    }
    __syncthreads();
    #pragma unroll
    for (int s = 64; s > 0; s >>= 1) {
        if (tid < s) sRED[tid] += sRED[tid + s];
        __syncthreads();
    }
    if (tid == 0) g_partial[blockIdx.x] = sRED[0];
}

// ---------------------------------------------------------------------------
// Kernel C: final loss reduce. e_latent == q_latent in value -> 1.25 * mean.
// ---------------------------------------------------------------------------
__global__ void finalize_kernel(float* __restrict__ out, int out_size) {
    __shared__ float red[GRID_M];
    red[threadIdx.x] = g_partial[threadIdx.x];
    __syncthreads();
    #pragma unroll
    for (int s = GRID_M / 2; s > 0; s >>= 1) {
        if (threadIdx.x < s) red[threadIdx.x] += red[threadIdx.x + s];
        __syncthreads();
    }
    if (threadIdx.x == 0) {
        out[0] = 1.25f * red[0] / (float)QELEMS;
        out[out_size - 1] = 0.0f;
    }
}

// ---------------------------------------------------------------------------
extern "C" void kernel_launch(void* const* d_in, const int* in_sizes, int n_in,
                              void* d_out, int out_size) {
    const float* in = (const float*)d_in[0];   // [B, D, T] float32
    const float* w  = (const float*)d_in[1];   // [K, D]    float32
    float* out = (float*)d_out;

    cudaFuncSetAttribute(vq_mma_kernel, cudaFuncAttributeMaxDynamicSharedMemorySize, SM_TOTAL);

    norm_weight_kernel<<<KK / 8, dim3(32, 8)>>>(w);
    vq_mma_kernel<<<GRID_M, 256, SM_TOTAL>>>(in, out);
    finalize_kernel<<<1, GRID_M>>>(out, out_size);
}

// round 6
// speedup vs baseline: 3.0720x; 1.9262x over previous
#include <cuda_runtime.h>
#include <cuda_fp16.h>
#include <cstdint>

// ---------------------------------------------------------------------------
// Problem constants
// ---------------------------------------------------------------------------
#define BB 32
#define DD 64
#define TT 2048
#define KK 1024
#define NN (BB * TT)              // 65536 rows
#define QELEMS (BB * DD * TT)     // 4194304
// Output (float32): [loss(1) | quantized(QELEMS) | indices(NN) | n_resurrected(1)]

#define TILE_M  128               // rows per CTA
#define CHUNK_N 128               // codewords per staged chunk
#define GRID_M  (NN / TILE_M)     // 512 CTAs
#define NCHUNK  (KK / CHUNK_N)    // 8

#define XS 68                     // sX row stride (floats)
#define BS 72                     // sB row stride (halves) -> conflict-free frags

// Dynamic smem layout (bytes)
#define SM_X     0                // 128 x 68 floats = 34816
#define SM_B     34816            // 128 x 72 halves = 18432
#define SM_CAND  53248            // 128 x 2 ints    = 1024
#define SM_RED   54272            // 256 floats      = 1024
#define SM_TOTAL 55296

__device__ float g_partial[GRID_M];
__device__ int   g_ctr;           // zero-initialized; reset by last block

// m16n8k16 fp16 MMA, fp32 accum, D += A*B
#define MMA_F16(d, a, b0, b1)                                                 \
    asm volatile("mma.sync.aligned.m16n8k16.row.col.f32.f16.f16.f32 "         \
                 "{%0,%1,%2,%3}, {%4,%5,%6,%7}, {%8,%9}, {%0,%1,%2,%3};"      \
                 : "+f"((d)[0]), "+f"((d)[1]), "+f"((d)[2]), "+f"((d)[3])     \
                 : "r"((a)[0]), "r"((a)[1]), "r"((a)[2]), "r"((a)[3]),        \
                   "r"(b0), "r"(b1))

__device__ __forceinline__ uint32_t pack_h2(float a, float b) {
    __half2 h = __floats2half2_rn(a, b);
    return *(uint32_t*)&h;
}

// ---------------------------------------------------------------------------
// Single fused kernel: normalize + fp16 mma dot matrix + pair top-2 +
// exact fp32 rescore + outputs + deterministic last-block loss finalize.
// ---------------------------------------------------------------------------
__global__ __launch_bounds__(256, 2)
void vq_all_kernel(const float* __restrict__ in, const float* __restrict__ w,
                   float* __restrict__ out, int out_size) {
    extern __shared__ char smem[];
    float*    sX    = (float*)(smem + SM_X);
    __half*   sB    = (__half*)(smem + SM_B);
    uint32_t* sB32  = (uint32_t*)(smem + SM_B);
    int*      sCand = (int*)(smem + SM_CAND);
    float*    sRED  = (float*)(smem + SM_RED);
    __shared__ int sLast;

    const int tid  = threadIdx.x;
    const int wid  = tid >> 5;
    const int lane = tid & 31;
    const int g    = lane >> 2;   // groupID (0..7)
    const int tig  = lane & 3;    // thread in group

    // ---- Phase 1: load + normalize 128 input rows into smem X (fp32) ----
    if (tid < TILE_M) {
        int n = blockIdx.x * TILE_M + tid;
        int b = n >> 11;
        int t = n & (TT - 1);
        const float* xp = in + (size_t)b * DD * TT + t;
        float x[DD];
        float ss = 0.0f;
        #pragma unroll
        for (int d = 0; d < DD; ++d) { float v = xp[(size_t)d * TT]; x[d] = v; ss += v * v; }
        float inv = 1.0f / fmaxf(sqrtf(ss), 1e-12f);
        #pragma unroll
        for (int d = 0; d < DD; ++d) sX[tid * XS + d] = x[d] * inv;
    }
    __syncthreads();

    // ---- Resident A fragments (fp16) for this warp's 16 rows ----
    const int rA = wid * 16 + g;
    const int rB = rA + 8;
    uint32_t A[4][4];
    #pragma unroll
    for (int c = 0; c < 4; ++c) {
        int k0 = c * 16 + 2 * tig;
        A[c][0] = pack_h2(sX[rA * XS + k0],     sX[rA * XS + k0 + 1]);
        A[c][1] = pack_h2(sX[rB * XS + k0],     sX[rB * XS + k0 + 1]);
        A[c][2] = pack_h2(sX[rA * XS + k0 + 8], sX[rA * XS + k0 + 9]);
        A[c][3] = pack_h2(sX[rB * XS + k0 + 8], sX[rB * XS + k0 + 9]);
    }

    const float NEGINF = -3.402823466e+38f;
    float bv0[2] = {NEGINF, NEGINF}, bv1[2] = {NEGINF, NEGINF};
    int   bp0[2] = {0, 0},           bp1[2] = {0, 0};

    const int cr = tid >> 1;      // conversion row (0..127)
    const int ch = tid & 1;       // conversion half

    for (int nt = 0; nt < NCHUNK; ++nt) {
        __syncthreads();   // previous chunk's B fully consumed

        // ---- Normalize + convert chunk nt of the codebook into sB (fp16) ----
        {
            const float4* src = (const float4*)(w + (size_t)(nt * CHUNK_N + cr) * DD + ch * 32);
            float4 v4[8];
            #pragma unroll
            for (int i = 0; i < 8; ++i) v4[i] = src[i];
            float ss = 0.0f;
            #pragma unroll
            for (int i = 0; i < 8; ++i)
                ss += v4[i].x * v4[i].x + v4[i].y * v4[i].y + v4[i].z * v4[i].z + v4[i].w * v4[i].w;
            ss += __shfl_xor_sync(0xFFFFFFFFu, ss, 1);   // combine the two row halves
            float inv = 1.0f / fmaxf(sqrtf(ss), 1e-12f);
            __half* dst = sB + cr * BS + ch * 32;
            #pragma unroll
            for (int i = 0; i < 8; ++i) {
                dst[i * 4 + 0] = __float2half_rn(v4[i].x * inv);
                dst[i * 4 + 1] = __float2half_rn(v4[i].y * inv);
                dst[i * 4 + 2] = __float2half_rn(v4[i].z * inv);
                dst[i * 4 + 3] = __float2half_rn(v4[i].w * inv);
            }
        }
        __syncthreads();

        const int pbase = nt * 64 + tig;   // pair-id base for this chunk

        // ---- 4 tile-pairs: B frag loads, 16 MMAs, pair-max top-2 select ----
        #pragma unroll
        for (int pp = 0; pp < 4; ++pp) {
            const int n0 = pp * 32;
            uint32_t b[2][2][4][2];
            #pragma unroll
            for (int c = 0; c < 4; ++c) {
                int o = (n0 + g) * (BS / 2) + c * 8 + tig;
                b[0][0][c][0] = sB32[o];
                b[0][0][c][1] = sB32[o + 4];
                b[0][1][c][0] = sB32[o + 8 * (BS / 2)];
                b[0][1][c][1] = sB32[o + 8 * (BS / 2) + 4];
                b[1][0][c][0] = sB32[o + 16 * (BS / 2)];
                b[1][0][c][1] = sB32[o + 16 * (BS / 2) + 4];
                b[1][1][c][0] = sB32[o + 24 * (BS / 2)];
                b[1][1][c][1] = sB32[o + 24 * (BS / 2) + 4];
            }
            float acc[2][2][4];
            #pragma unroll
            for (int q = 0; q < 2; ++q)
                #pragma unroll
                for (int h = 0; h < 2; ++h)
                    #pragma unroll
                    for (int e = 0; e < 4; ++e) acc[q][h][e] = 0.0f;
            #pragma unroll
            for (int c = 0; c < 4; ++c) {
                MMA_F16(acc[0][0], A[c], b[0][0][c][0], b[0][0][c][1]);
                MMA_F16(acc[0][1], A[c], b[0][1][c][0], b[0][1][c][1]);
                MMA_F16(acc[1][0], A[c], b[1][0][c][0], b[1][0][c][1]);
                MMA_F16(acc[1][1], A[c], b[1][1][c][0], b[1][1][c][1]);
            }
            // pair-max (2 same-row columns) then top-2 over pairs per row
            #pragma unroll
            for (int q = 0; q < 2; ++q) {
                #pragma unroll
                for (int h = 0; h < 2; ++h) {
                    const int pi = pbase + pp * 16 + q * 8 + h * 4;
                    float vA = fmaxf(acc[q][h][0], acc[q][h][1]);   // row rA
                    float vB = fmaxf(acc[q][h][2], acc[q][h][3]);   // row rB
                    if (vA > bv0[0])      { bv1[0] = bv0[0]; bp1[0] = bp0[0]; bv0[0] = vA; bp0[0] = pi; }
                    else if (vA > bv1[0]) { bv1[0] = vA; bp1[0] = pi; }
                    if (vB > bv0[1])      { bv1[1] = bv0[1]; bp1[1] = bp0[1]; bv0[1] = vB; bp0[1] = pi; }
                    else if (vB > bv1[1]) { bv1[1] = vB; bp1[1] = pi; }
                }
            }
        }
    }

    // ---- Merge top-2 pair lists across the 4 lanes of each group ----
    #pragma unroll
    for (int r = 0; r < 2; ++r) {
        #pragma unroll
        for (int off = 1; off <= 2; off <<= 1) {
            float vb = __shfl_xor_sync(0xFFFFFFFFu, bv0[r], off);
            int   ib = __shfl_xor_sync(0xFFFFFFFFu, bp0[r], off);
            float vs = __shfl_xor_sync(0xFFFFFFFFu, bv1[r], off);
            int   is = __shfl_xor_sync(0xFFFFFFFFu, bp1[r], off);
            if (vb > bv0[r]) {
                if (bv0[r] >= vs) { bv1[r] = bv0[r]; bp1[r] = bp0[r]; }
                else              { bv1[r] = vs;      bp1[r] = is; }
                bv0[r] = vb; bp0[r] = ib;
            } else if (vb > bv1[r]) {
                bv1[r] = vb; bp1[r] = ib;
            }
        }
        if (tig == 0) {
            int row = (r == 0) ? rA : rB;
            sCand[row * 2 + 0] = bp0[r];
            sCand[row * 2 + 1] = bp1[r];
        }
    }
    __syncthreads();

    // ---- Exact fp32 rescore of 4 candidate columns + outputs ----
    if (tid < TILE_M) {
        int n = blockIdx.x * TILE_M + tid;
        int b = n >> 11;
        int t = n & (TT - 1);
        int p0 = sCand[tid * 2], p1 = sCand[tid * 2 + 1];
        int cand[4] = {2 * p0, 2 * p0 + 1, 2 * p1, 2 * p1 + 1};
        const float* xr = sX + tid * XS;
        float best = NEGINF;
        int   bi   = KK;
        #pragma unroll
        for (int c = 0; c < 4; ++c) {
            int idx = cand[c];
            const float4* wp = (const float4*)(w + (size_t)idx * DD);
            float ss = 0.0f, dot = 0.0f;
            #pragma unroll
            for (int i = 0; i < 16; ++i) {
                float4 v = wp[i];
                ss  += v.x * v.x + v.y * v.y + v.z * v.z + v.w * v.w;
                dot += v.x * xr[i * 4] + v.y * xr[i * 4 + 1] + v.z * xr[i * 4 + 2] + v.w * xr[i * 4 + 3];
            }
            float d = dot * (1.0f / fmaxf(sqrtf(ss), 1e-12f));
            if (d > best || (d == best && idx < bi)) { best = d; bi = idx; }
        }
        // gather selected codeword (normalize exactly), write quantized + index
        const float4* wp = (const float4*)(w + (size_t)bi * DD);
        float ss = 0.0f;
        #pragma unroll
        for (int i = 0; i < 16; ++i) {
            float4 v = wp[i];
            ss += v.x * v.x + v.y * v.y + v.z * v.z + v.w * v.w;
        }
        float inv = 1.0f / fmaxf(sqrtf(ss), 1e-12f);
        float* qp = out + 1 + (size_t)b * DD * TT + t;
        float err = 0.0f;
        #pragma unroll
        for (int i = 0; i < 16; ++i) {
            float4 v = wp[i];
            float q0 = v.x * inv, q1 = v.y * inv, q2 = v.z * inv, q3 = v.w * inv;
            qp[(size_t)(i * 4 + 0) * TT] = q0;
            qp[(size_t)(i * 4 + 1) * TT] = q1;
            qp[(size_t)(i * 4 + 2) * TT] = q2;
            qp[(size_t)(i * 4 + 3) * TT] = q3;
            float e0 = q0 - xr[i * 4],     e1 = q1 - xr[i * 4 + 1];
            float e2 = q2 - xr[i * 4 + 2], e3 = q3 - xr[i * 4 + 3];
            err += e0 * e0 + e1 * e1 + e2 * e2 + e3 * e3;
        }
        out[1 + QELEMS + n] = (float)bi;
        sRED[tid] = err;
    }
    __syncthreads();
    #pragma unroll
    for (int s = 64; s > 0; s >>= 1) {
        if (tid < s) sRED[tid] += sRED[tid + s];
        __syncthreads();
    }
    if (tid == 0) g_partial[blockIdx.x] = sRED[0];

    // ---- Deterministic last-block loss finalize ----
    if (tid == 0) {
        __threadfence();
        int old = atomicAdd(&g_ctr, 1);
        sLast = (old == GRID_M - 1) ? 1 : 0;
    }
    __syncthreads();
    if (sLast) {
        float v = g_partial[tid] + g_partial[tid + 256];
        sRED[tid] = v;
        __syncthreads();
        #pragma unroll
        for (int s = 128; s > 0; s >>= 1) {
            if (tid < s) sRED[tid] += sRED[tid + s];
            __syncthreads();
        }
        if (tid == 0) {
            out[0] = 1.25f * sRED[0] / (float)QELEMS;   // q_loss + 0.25*e_loss, equal in value
            out[out_size - 1] = 0.0f;                   // n_resurrected
            g_ctr = 0;                                  // reset for next graph replay
        }
    }
}

// ---------------------------------------------------------------------------
extern "C" void kernel_launch(void* const* d_in, const int* in_sizes, int n_in,
                              void* d_out, int out_size) {
    const float* in = (const float*)d_in[0];   // [B, D, T] float32
    const float* w  = (const float*)d_in[1];   // [K, D]    float32
    float* out = (float*)d_out;

    cudaFuncSetAttribute(vq_all_kernel, cudaFuncAttributeMaxDynamicSharedMemorySize, SM_TOTAL);
    vq_all_kernel<<<GRID_M, 256, SM_TOTAL>>>(in, w, out, out_size);
}

// round 7
// speedup vs baseline: 4.2314x; 1.3774x over previous
#include <cuda_runtime.h>
#include <cuda_fp16.h>
#include <cstdint>

// ---------------------------------------------------------------------------
// Problem constants
// ---------------------------------------------------------------------------
#define BB 32
#define DD 64
#define TT 2048
#define KK 1024
#define NN (BB * TT)              // 65536 rows
#define QELEMS (BB * DD * TT)     // 4194304
// Output (float32): [loss(1) | quantized(QELEMS) | indices(NN) | n_resurrected(1)]

#define TILE_M  256               // rows per CTA (32 per warp)
#define CHUNK_N 128               // codewords per staged chunk
#define GRID_M  (NN / TILE_M)     // 256 CTAs
#define NCHUNK  (KK / CHUNK_N)    // 8

#define XS 68                     // sX row stride (floats)
#define BS 72                     // sB row stride (halves) -> conflict-free frags
#define BSW (BS / 2)              // 36 words

// Dynamic smem layout (bytes)
#define SM_X     0                // 256 x 68 floats = 69632
#define SM_B     69632            // 128 x 72 halves = 18432
#define SM_CAND  88064            // 256 x 2 ints    = 2048
#define SM_RED   90112            // 256 floats      = 1024
#define SM_TOTAL 91136

__device__ float g_partial[GRID_M];
__device__ int   g_ctr;           // zero-initialized; reset by last block

// m16n8k16 fp16 MMA, fp32 accum, D += A*B
#define MMA_F16(d, a, b0, b1)                                                 \
    asm volatile("mma.sync.aligned.m16n8k16.row.col.f32.f16.f16.f32 "         \
                 "{%0,%1,%2,%3}, {%4,%5,%6,%7}, {%8,%9}, {%0,%1,%2,%3};"      \
                 : "+f"((d)[0]), "+f"((d)[1]), "+f"((d)[2]), "+f"((d)[3])     \
                 : "r"((a)[0]), "r"((a)[1]), "r"((a)[2]), "r"((a)[3]),        \
                   "r"(b0), "r"(b1))

__device__ __forceinline__ uint32_t pack_h2(float a, float b) {
    __half2 h = __floats2half2_rn(a, b);
    return *(uint32_t*)&h;
}

// ---------------------------------------------------------------------------
// Single fused kernel
// ---------------------------------------------------------------------------
__global__ __launch_bounds__(256, 2)
void vq_all_kernel(const float* __restrict__ in, const float* __restrict__ w,
                   float* __restrict__ out, int out_size) {
    extern __shared__ char smem[];
    float*    sX    = (float*)(smem + SM_X);
    __half*   sB    = (__half*)(smem + SM_B);
    uint32_t* sB32  = (uint32_t*)(smem + SM_B);
    int*      sCand = (int*)(smem + SM_CAND);
    float*    sRED  = (float*)(smem + SM_RED);
    __shared__ int sLast;

    const int tid  = threadIdx.x;
    const int wid  = tid >> 5;
    const int lane = tid & 31;
    const int g    = lane >> 2;   // groupID (0..7)
    const int tig  = lane & 3;    // thread in group

    // ---- Phase 1: load + normalize 256 input rows into smem X (fp32) ----
    {
        int n = blockIdx.x * TILE_M + tid;
        int b = n >> 11;
        int t = n & (TT - 1);
        const float* xp = in + (size_t)b * DD * TT + t;
        float x[DD];
        float ss = 0.0f;
        #pragma unroll
        for (int d = 0; d < DD; ++d) { float v = xp[(size_t)d * TT]; x[d] = v; ss += v * v; }
        float inv = 1.0f / fmaxf(sqrtf(ss), 1e-12f);
        #pragma unroll
        for (int d = 0; d < DD; ++d) sX[tid * XS + d] = x[d] * inv;
    }
    __syncthreads();

    // ---- Resident A fragments (fp16) for this warp's 32 rows (2 groups) ----
    const int rbase = wid * 32;
    uint32_t A[2][4][4];
    #pragma unroll
    for (int grp = 0; grp < 2; ++grp) {
        const int r0 = rbase + grp * 16 + g;
        const int r1 = r0 + 8;
        #pragma unroll
        for (int c = 0; c < 4; ++c) {
            int k0 = c * 16 + 2 * tig;
            A[grp][c][0] = pack_h2(sX[r0 * XS + k0],     sX[r0 * XS + k0 + 1]);
            A[grp][c][1] = pack_h2(sX[r1 * XS + k0],     sX[r1 * XS + k0 + 1]);
            A[grp][c][2] = pack_h2(sX[r0 * XS + k0 + 8], sX[r0 * XS + k0 + 9]);
            A[grp][c][3] = pack_h2(sX[r1 * XS + k0 + 8], sX[r1 * XS + k0 + 9]);
        }
    }

    const float NEGINF = -3.402823466e+38f;
    float bv0[4] = {NEGINF, NEGINF, NEGINF, NEGINF};
    float bv1[4] = {NEGINF, NEGINF, NEGINF, NEGINF};
    int   bp0[4] = {0, 0, 0, 0}, bp1[4] = {0, 0, 0, 0};

    const int cr = tid >> 1;      // conversion row (0..127)
    const int ch = tid & 1;       // conversion half

    #pragma unroll 1
    for (int nt = 0; nt < NCHUNK; ++nt) {
        __syncthreads();   // previous chunk's B fully consumed

        // ---- Normalize + convert chunk nt of the codebook into sB (fp16) ----
        {
            const float4* src = (const float4*)(w + (size_t)(nt * CHUNK_N + cr) * DD + ch * 32);
            float4 v4[8];
            #pragma unroll
            for (int i = 0; i < 8; ++i) v4[i] = src[i];
            float ss = 0.0f;
            #pragma unroll
            for (int i = 0; i < 8; ++i)
                ss += v4[i].x * v4[i].x + v4[i].y * v4[i].y + v4[i].z * v4[i].z + v4[i].w * v4[i].w;
            ss += __shfl_xor_sync(0xFFFFFFFFu, ss, 1);   // combine the two row halves
            float inv = 1.0f / fmaxf(sqrtf(ss), 1e-12f);
            __half* dst = sB + cr * BS + ch * 32;
            #pragma unroll
            for (int i = 0; i < 8; ++i) {
                dst[i * 4 + 0] = __float2half_rn(v4[i].x * inv);
                dst[i * 4 + 1] = __float2half_rn(v4[i].y * inv);
                dst[i * 4 + 2] = __float2half_rn(v4[i].z * inv);
                dst[i * 4 + 3] = __float2half_rn(v4[i].w * inv);
            }
        }
        __syncthreads();

        // ---- 8 sub-tiles of 16 codewords: B frags feed BOTH row groups ----
        #pragma unroll
        for (int pp = 0; pp < 8; ++pp) {
            const int n0 = pp * 16;
            uint32_t b[2][4][2];            // [h][c][half]
            #pragma unroll
            for (int c = 0; c < 4; ++c) {
                int o = (n0 + g) * BSW + c * 8 + tig;
                b[0][c][0] = sB32[o];
                b[0][c][1] = sB32[o + 4];
                b[1][c][0] = sB32[o + 8 * BSW];
                b[1][c][1] = sB32[o + 8 * BSW + 4];
            }
            float acc[2][2][4];             // [grp][h][e]
            #pragma unroll
            for (int grp = 0; grp < 2; ++grp)
                #pragma unroll
                for (int h = 0; h < 2; ++h)
                    #pragma unroll
                    for (int e = 0; e < 4; ++e) acc[grp][h][e] = 0.0f;
            #pragma unroll
            for (int c = 0; c < 4; ++c) {
                MMA_F16(acc[0][0], A[0][c], b[0][c][0], b[0][c][1]);
                MMA_F16(acc[0][1], A[0][c], b[1][c][0], b[1][c][1]);
                MMA_F16(acc[1][0], A[1][c], b[0][c][0], b[0][c][1]);
                MMA_F16(acc[1][1], A[1][c], b[1][c][0], b[1][c][1]);
            }
            // pair-max then top-2 over pairs, per row (4 rows per lane)
            #pragma unroll
            for (int grp = 0; grp < 2; ++grp) {
                #pragma unroll
                for (int h = 0; h < 2; ++h) {
                    const int pi = nt * 64 + pp * 8 + h * 4 + tig;
                    float vA = fmaxf(acc[grp][h][0], acc[grp][h][1]);   // row rbase+grp*16+g
                    float vB = fmaxf(acc[grp][h][2], acc[grp][h][3]);   // row +8
                    const int rY = grp * 2;
                    if (vA > bv0[rY])      { bv1[rY] = bv0[rY]; bp1[rY] = bp0[rY]; bv0[rY] = vA; bp0[rY] = pi; }
                    else if (vA > bv1[rY]) { bv1[rY] = vA; bp1[rY] = pi; }
                    const int rZ = rY + 1;
                    if (vB > bv0[rZ])      { bv1[rZ] = bv0[rZ]; bp1[rZ] = bp0[rZ]; bv0[rZ] = vB; bp0[rZ] = pi; }
                    else if (vB > bv1[rZ]) { bv1[rZ] = vB; bp1[rZ] = pi; }
                }
            }
        }
    }

    // ---- Merge top-2 pair lists across the 4 lanes of each group ----
    #pragma unroll
    for (int r = 0; r < 4; ++r) {
        #pragma unroll
        for (int off = 1; off <= 2; off <<= 1) {
            float vb = __shfl_xor_sync(0xFFFFFFFFu, bv0[r], off);
            int   ib = __shfl_xor_sync(0xFFFFFFFFu, bp0[r], off);
            float vs = __shfl_xor_sync(0xFFFFFFFFu, bv1[r], off);
            int   is = __shfl_xor_sync(0xFFFFFFFFu, bp1[r], off);
            if (vb > bv0[r]) {
                if (bv0[r] >= vs) { bv1[r] = bv0[r]; bp1[r] = bp0[r]; }
                else              { bv1[r] = vs;      bp1[r] = is; }
                bv0[r] = vb; bp0[r] = ib;
            } else if (vb > bv1[r]) {
                bv1[r] = vb; bp1[r] = ib;
            }
        }
        if (tig == 0) {
            int row = rbase + (r >> 1) * 16 + (r & 1) * 8 + g;
            sCand[row * 2 + 0] = bp0[r];
            sCand[row * 2 + 1] = bp1[r];
        }
    }
    __syncthreads();

    // ---- Cooperative exact fp32 rescore: group g handles 4 rows ----
    // Lane tig loads dims [16*tig, 16*tig+16) -> contiguous 64B per group.
    #pragma unroll 1
    for (int s = 0; s < 4; ++s) {
        const int row = rbase + g * 4 + s;
        const int p0 = sCand[row * 2], p1 = sCand[row * 2 + 1];
        int cand[4] = {2 * p0, 2 * p0 + 1, 2 * p1, 2 * p1 + 1};
        float4 xq[4];
        #pragma unroll
        for (int j = 0; j < 4; ++j)
            xq[j] = *(const float4*)(sX + row * XS + tig * 16 + j * 4);
        float best = NEGINF;
        int   bi   = KK;
        #pragma unroll
        for (int c = 0; c < 4; ++c) {
            const int idx = cand[c];
            const float4* wp = (const float4*)(w + (size_t)idx * DD) + tig * 4;
            float dot = 0.0f, ssw = 0.0f;
            #pragma unroll
            for (int j = 0; j < 4; ++j) {
                float4 v = wp[j];
                dot += v.x * xq[j].x + v.y * xq[j].y + v.z * xq[j].z + v.w * xq[j].w;
                ssw += v.x * v.x + v.y * v.y + v.z * v.z + v.w * v.w;
            }
            dot += __shfl_xor_sync(0xFFFFFFFFu, dot, 1);
            ssw += __shfl_xor_sync(0xFFFFFFFFu, ssw, 1);
            dot += __shfl_xor_sync(0xFFFFFFFFu, dot, 2);
            ssw += __shfl_xor_sync(0xFFFFFFFFu, ssw, 2);
            float d = dot * (1.0f / fmaxf(sqrtf(ssw), 1e-12f));
            if (d > best || (d == best && idx < bi)) { best = d; bi = idx; }
        }
        if (tig == 0) sCand[row * 2] = bi;   // final index for this row
    }
    __syncthreads();

    // ---- Winner phase (per-thread, keeps quantized STG coalesced) ----
    {
        int n = blockIdx.x * TILE_M + tid;
        int b = n >> 11;
        int t = n & (TT - 1);
        int bi = sCand[tid * 2];
        const float4* wp = (const float4*)(w + (size_t)bi * DD);
        const float* xr = sX + tid * XS;
        float ss = 0.0f;
        #pragma unroll
        for (int i = 0; i < 16; ++i) {
            float4 v = wp[i];
            ss += v.x * v.x + v.y * v.y + v.z * v.z + v.w * v.w;
        }
        float inv = 1.0f / fmaxf(sqrtf(ss), 1e-12f);
        float* qp = out + 1 + (size_t)b * DD * TT + t;
        float err = 0.0f;
        #pragma unroll
        for (int i = 0; i < 16; ++i) {
            float4 v = wp[i];
            float q0 = v.x * inv, q1 = v.y * inv, q2 = v.z * inv, q3 = v.w * inv;
            qp[(size_t)(i * 4 + 0) * TT] = q0;
            qp[(size_t)(i * 4 + 1) * TT] = q1;
            qp[(size_t)(i * 4 + 2) * TT] = q2;
            qp[(size_t)(i * 4 + 3) * TT] = q3;
            float e0 = q0 - xr[i * 4],     e1 = q1 - xr[i * 4 + 1];
            float e2 = q2 - xr[i * 4 + 2], e3 = q3 - xr[i * 4 + 3];
            err += e0 * e0 + e1 * e1 + e2 * e2 + e3 * e3;
        }
        out[1 + QELEMS + n] = (float)bi;
        sRED[tid] = err;
    }
    __syncthreads();
    #pragma unroll
    for (int s = 128; s > 0; s >>= 1) {
        if (tid < s) sRED[tid] += sRED[tid + s];
        __syncthreads();
    }
    if (tid == 0) g_partial[blockIdx.x] = sRED[0];

    // ---- Deterministic last-block loss finalize ----
    if (tid == 0) {
        __threadfence();
        int old = atomicAdd(&g_ctr, 1);
        sLast = (old == GRID_M - 1) ? 1 : 0;
    }
    __syncthreads();
    if (sLast) {
        sRED[tid] = g_partial[tid];
        __syncthreads();
        #pragma unroll
        for (int s = 128; s > 0; s >>= 1) {
            if (tid < s) sRED[tid] += sRED[tid + s];
            __syncthreads();
        }
        if (tid == 0) {
            out[0] = 1.25f * sRED[0] / (float)QELEMS;   // q_loss + 0.25*e_loss, equal in value
            out[out_size - 1] = 0.0f;                   // n_resurrected
            g_ctr = 0;                                  // reset for next graph replay
        }
    }
}

// ---------------------------------------------------------------------------
extern "C" void kernel_launch(void* const* d_in, const int* in_sizes, int n_in,
                              void* d_out, int out_size) {
    const float* in = (const float*)d_in[0];   // [B, D, T] float32
    const float* w  = (const float*)d_in[1];   // [K, D]    float32
    float* out = (float*)d_out;

    cudaFuncSetAttribute(vq_all_kernel, cudaFuncAttributeMaxDynamicSharedMemorySize, SM_TOTAL);
    vq_all_kernel<<<GRID_M, 256, SM_TOTAL>>>(in, w, out, out_size);
}

// round 8
// speedup vs baseline: 5.1567x; 1.2187x over previous
#include <cuda_runtime.h>
#include <cuda_fp16.h>
#include <cstdint>

// ---------------------------------------------------------------------------
// Problem constants
// ---------------------------------------------------------------------------
#define BB 32
#define DD 64
#define TT 2048
#define KK 1024
#define NN (BB * TT)              // 65536 rows
#define QELEMS (BB * DD * TT)     // 4194304
// Output (float32): [loss(1) | quantized(QELEMS) | indices(NN) | n_resurrected(1)]

#define TILE_M  256               // rows per CTA (32 per warp)
#define CHUNK_N 128               // codewords per staged chunk
#define GRID_M  (NN / TILE_M)     // 256 CTAs
#define NCHUNK  (KK / CHUNK_N)    // 8

#define BS 72                     // sB row stride in halves (144 B)

// Dynamic smem layout (bytes)
#define SM_X     0                // 256 x 64 floats (xor-swizzled) = 65536
#define SM_B     65536            // 128 x 72 halves = 18432
#define SM_CAND  83968            // 256 x 2 ints    = 2048
#define SM_RED   86016            // 256 floats      = 1024
#define SM_TOTAL 87040

__device__ float g_partial[GRID_M];
__device__ int   g_ctr;           // zero-initialized; reset by last block

// m16n8k16 fp16 MMA, fp32 accum, D += A*B
#define MMA_F16(d, a, b0, b1)                                                 \
    asm volatile("mma.sync.aligned.m16n8k16.row.col.f32.f16.f16.f32 "         \
                 "{%0,%1,%2,%3}, {%4,%5,%6,%7}, {%8,%9}, {%0,%1,%2,%3};"      \
                 : "+f"((d)[0]), "+f"((d)[1]), "+f"((d)[2]), "+f"((d)[3])     \
                 : "r"((a)[0]), "r"((a)[1]), "r"((a)[2]), "r"((a)[3]),        \
                   "r"(b0), "r"(b1))

#define LDSM4(r, a)                                                           \
    asm volatile("ldmatrix.sync.aligned.m8n8.x4.shared.b16 {%0,%1,%2,%3}, [%4];" \
                 : "=r"((r)[0]), "=r"((r)[1]), "=r"((r)[2]), "=r"((r)[3])     \
                 : "r"(a))

__device__ __forceinline__ uint32_t smem_to_u32(const void* p) {
    uint32_t a;
    asm("{ .reg .u64 t; cvta.to.shared.u64 t, %1; cvt.u32.u64 %0, t; }" : "=r"(a) : "l"(p));
    return a;
}
__device__ __forceinline__ uint32_t pack_h2(float a, float b) {
    __half2 h = __floats2half2_rn(a, b);
    return *(uint32_t*)&h;
}
// monotone fp32 -> u32 (unsigned compare order == float order)
__device__ __forceinline__ uint32_t fkey(float v) {
    int s = __float_as_int(v);
    return (uint32_t)(s ^ ((s >> 31) | 0x80000000));
}

// ---------------------------------------------------------------------------
// Single fused kernel
// ---------------------------------------------------------------------------
__global__ __launch_bounds__(256, 2)
void vq_all_kernel(const float* __restrict__ in, const float* __restrict__ w,
                   float* __restrict__ out, int out_size) {
    extern __shared__ char smem[];
    float*    sX    = (float*)(smem + SM_X);
    __half*   sB    = (__half*)(smem + SM_B);
    int*      sCand = (int*)(smem + SM_CAND);
    float*    sRED  = (float*)(smem + SM_RED);
    __shared__ int sLast;

    const int tid  = threadIdx.x;
    const int wid  = tid >> 5;
    const int lane = tid & 31;
    const int g    = lane >> 2;   // groupID (0..7)
    const int tig  = lane & 3;    // thread in group
    const int lr   = lane & 7;    // ldmatrix row
    const int lj   = lane >> 3;   // ldmatrix tile

    // ---- Phase 1: load + normalize 256 rows into xor-swizzled smem X ----
    {
        int n = blockIdx.x * TILE_M + tid;
        int b = n >> 11;
        int t = n & (TT - 1);
        const float* xp = in + (size_t)b * DD * TT + t;
        float x[DD];
        float ss = 0.0f;
        #pragma unroll
        for (int d = 0; d < DD; ++d) { float v = xp[(size_t)d * TT]; x[d] = v; ss += v * v; }
        float inv = 1.0f / fmaxf(sqrtf(ss), 1e-12f);
        const int sw = tid & 15;
        #pragma unroll
        for (int cd = 0; cd < 16; ++cd) {
            *(float4*)(sX + tid * 64 + ((cd ^ sw) << 2)) =
                make_float4(x[4 * cd] * inv, x[4 * cd + 1] * inv,
                            x[4 * cd + 2] * inv, x[4 * cd + 3] * inv);
        }
    }
    __syncthreads();

    // ---- Resident A fragments (fp16) for this warp's 32 rows (2 groups) ----
    const int rbase = wid * 32;
    uint32_t A[2][4][4];
    #pragma unroll
    for (int grp = 0; grp < 2; ++grp) {
        const int r0 = rbase + grp * 16 + g;
        const int r1 = r0 + 8;
        const int s0 = r0 & 15, s1 = r1 & 15;
        #pragma unroll
        for (int c = 0; c < 4; ++c) {
            const int ch0 = c * 4 + (tig >> 1);        // chunk of k0 = 16c + 2tig
            const int off = (2 * tig) & 3;
            const float* pa = sX + r0 * 64 + ((ch0 ^ s0) << 2) + off;
            const float* pb = sX + r1 * 64 + ((ch0 ^ s1) << 2) + off;
            const float* pa8 = sX + r0 * 64 + (((ch0 + 2) ^ s0) << 2) + off;
            const float* pb8 = sX + r1 * 64 + (((ch0 + 2) ^ s1) << 2) + off;
            A[grp][c][0] = pack_h2(pa[0],  pa[1]);
            A[grp][c][1] = pack_h2(pb[0],  pb[1]);
            A[grp][c][2] = pack_h2(pa8[0], pa8[1]);
            A[grp][c][3] = pack_h2(pb8[0], pb8[1]);
        }
    }

    uint32_t k0[4] = {0, 0, 0, 0}, k1[4] = {0, 0, 0, 0};   // packed top-2 keys

    const int cr = tid >> 1;      // conversion row (0..127)
    const int ch = tid & 1;       // conversion half
    const uint32_t ldsm_base = smem_to_u32(sB) + (uint32_t)(lr * 144 + lj * 16);

    #pragma unroll 1
    for (int nt = 0; nt < NCHUNK; ++nt) {
        __syncthreads();   // previous chunk's B fully consumed

        // ---- Normalize + convert chunk nt of codebook into sB (fp16) ----
        {
            const float4* src = (const float4*)(w + (size_t)(nt * CHUNK_N + cr) * DD + ch * 32);
            float4 v4[8];
            #pragma unroll
            for (int i = 0; i < 8; ++i) v4[i] = src[i];
            float ss = 0.0f;
            #pragma unroll
            for (int i = 0; i < 8; ++i)
                ss += v4[i].x * v4[i].x + v4[i].y * v4[i].y + v4[i].z * v4[i].z + v4[i].w * v4[i].w;
            ss += __shfl_xor_sync(0xFFFFFFFFu, ss, 1);   // combine row halves
            float inv = 1.0f / fmaxf(sqrtf(ss), 1e-12f);
            uint32_t p[16];
            #pragma unroll
            for (int i = 0; i < 8; ++i) {
                p[2 * i]     = pack_h2(v4[i].x * inv, v4[i].y * inv);
                p[2 * i + 1] = pack_h2(v4[i].z * inv, v4[i].w * inv);
            }
            uint4* dst = (uint4*)(sB + cr * BS + ch * 32);
            #pragma unroll
            for (int s = 0; s < 4; ++s)
                dst[s] = make_uint4(p[4 * s], p[4 * s + 1], p[4 * s + 2], p[4 * s + 3]);
        }
        __syncthreads();

        // ---- 8 sub-tiles of 16 codewords ----
        #pragma unroll
        for (int pp = 0; pp < 8; ++pp) {
            const int n0 = pp * 16;
            uint32_t Bf[4][4];                       // [h*2+seg][tile]
            const uint32_t a0 = ldsm_base + (uint32_t)(n0 * 144);
            LDSM4(Bf[0], a0);                        // h0, k 0..31
            LDSM4(Bf[1], a0 + 64);                   // h0, k 32..63
            LDSM4(Bf[2], a0 + 8 * 144);              // h1, k 0..31
            LDSM4(Bf[3], a0 + 8 * 144 + 64);         // h1, k 32..63

            float acc[2][2][4];
            #pragma unroll
            for (int grp = 0; grp < 2; ++grp)
                #pragma unroll
                for (int h = 0; h < 2; ++h)
                    #pragma unroll
                    for (int e = 0; e < 4; ++e) acc[grp][h][e] = 0.0f;
            #pragma unroll
            for (int c = 0; c < 4; ++c) {
                const int bi_ = c >> 1;
                const int be  = (c & 1) * 2;
                MMA_F16(acc[0][0], A[0][c], Bf[bi_][be],     Bf[bi_][be + 1]);
                MMA_F16(acc[0][1], A[0][c], Bf[2 + bi_][be], Bf[2 + bi_][be + 1]);
                MMA_F16(acc[1][0], A[1][c], Bf[bi_][be],     Bf[bi_][be + 1]);
                MMA_F16(acc[1][1], A[1][c], Bf[2 + bi_][be], Bf[2 + bi_][be + 1]);
            }
            // pair-max -> packed key -> branch-free top-2 (3 IMNMX per update)
            #pragma unroll
            for (int grp = 0; grp < 2; ++grp) {
                #pragma unroll
                for (int h = 0; h < 2; ++h) {
                    const uint32_t code = 1023u - (uint32_t)(nt * 64 + pp * 8 + h * 4 + tig);
                    float vA = fmaxf(acc[grp][h][0], acc[grp][h][1]);
                    float vB = fmaxf(acc[grp][h][2], acc[grp][h][3]);
                    uint32_t kA = (fkey(vA) & 0xFFFFFC00u) | code;
                    uint32_t kB = (fkey(vB) & 0xFFFFFC00u) | code;
                    const int rY = grp * 2, rZ = rY + 1;
                    uint32_t tA = min(k0[rY], kA);
                    k0[rY] = max(k0[rY], kA);
                    k1[rY] = max(k1[rY], tA);
                    uint32_t tB = min(k0[rZ], kB);
                    k0[rZ] = max(k0[rZ], kB);
                    k1[rZ] = max(k1[rZ], tB);
                }
            }
        }
    }

    // ---- Merge top-2 key sets across the 4 lanes of each group ----
    #pragma unroll
    for (int r = 0; r < 4; ++r) {
        #pragma unroll
        for (int off = 1; off <= 2; off <<= 1) {
            uint32_t o0 = __shfl_xor_sync(0xFFFFFFFFu, k0[r], off);
            uint32_t o1 = __shfl_xor_sync(0xFFFFFFFFu, k1[r], off);
            uint32_t mn = min(k0[r], o0);
            k0[r] = max(k0[r], o0);
            k1[r] = max(max(k1[r], o1), mn);
        }
        if (tig == 0) {
            int row = rbase + (r >> 1) * 16 + (r & 1) * 8 + g;
            sCand[row * 2 + 0] = 1023 - (int)(k0[r] & 1023u);
            sCand[row * 2 + 1] = 1023 - (int)(k1[r] & 1023u);
        }
    }
    __syncthreads();

    // ---- Cooperative exact fp32 rescore: group g handles 4 rows ----
    const float NEGINF = -3.402823466e+38f;
    #pragma unroll 1
    for (int s = 0; s < 4; ++s) {
        const int row = rbase + g * 4 + s;
        const int sw  = row & 15;
        const int p0 = sCand[row * 2], p1 = sCand[row * 2 + 1];
        int cand[4] = {2 * p0, 2 * p0 + 1, 2 * p1, 2 * p1 + 1};
        float4 xq[4];
        #pragma unroll
        for (int j = 0; j < 4; ++j)
            xq[j] = *(const float4*)(sX + row * 64 + (((tig * 4 + j) ^ sw) << 2));
        float best = NEGINF;
        int   bi   = KK;
        #pragma unroll
        for (int c = 0; c < 4; ++c) {
            const int idx = cand[c];
            const float4* wp = (const float4*)(w + (size_t)idx * DD) + tig * 4;
            float dot = 0.0f, ssw = 0.0f;
            #pragma unroll
            for (int j = 0; j < 4; ++j) {
                float4 v = wp[j];
                dot += v.x * xq[j].x + v.y * xq[j].y + v.z * xq[j].z + v.w * xq[j].w;
                ssw += v.x * v.x + v.y * v.y + v.z * v.z + v.w * v.w;
            }
            dot += __shfl_xor_sync(0xFFFFFFFFu, dot, 1);
            ssw += __shfl_xor_sync(0xFFFFFFFFu, ssw, 1);
            dot += __shfl_xor_sync(0xFFFFFFFFu, dot, 2);
            ssw += __shfl_xor_sync(0xFFFFFFFFu, ssw, 2);
            float d = dot * (1.0f / fmaxf(sqrtf(ssw), 1e-12f));
            if (d > best || (d == best && idx < bi)) { best = d; bi = idx; }
        }
        if (tig == 0) sCand[row * 2] = bi;   // final index for this row
    }
    __syncthreads();

    // ---- Winner phase (per-thread; quantized STG stays t-coalesced) ----
    {
        int n = blockIdx.x * TILE_M + tid;
        int b = n >> 11;
        int t = n & (TT - 1);
        int bi = sCand[tid * 2];
        const float4* wp = (const float4*)(w + (size_t)bi * DD);
        const int sw = tid & 15;
        float ss = 0.0f;
        #pragma unroll
        for (int i = 0; i < 16; ++i) {
            float4 v = wp[i];
            ss += v.x * v.x + v.y * v.y + v.z * v.z + v.w * v.w;
        }
        float inv = 1.0f / fmaxf(sqrtf(ss), 1e-12f);
        float* qp = out + 1 + (size_t)b * DD * TT + t;
        float err = 0.0f;
        #pragma unroll
        for (int i = 0; i < 16; ++i) {
            float4 v = wp[i];
            float4 xv = *(const float4*)(sX + tid * 64 + ((i ^ sw) << 2));
            float q0 = v.x * inv, q1 = v.y * inv, q2 = v.z * inv, q3 = v.w * inv;
            qp[(size_t)(i * 4 + 0) * TT] = q0;
            qp[(size_t)(i * 4 + 1) * TT] = q1;
            qp[(size_t)(i * 4 + 2) * TT] = q2;
            qp[(size_t)(i * 4 + 3) * TT] = q3;
            float e0 = q0 - xv.x, e1 = q1 - xv.y, e2 = q2 - xv.z, e3 = q3 - xv.w;
            err += e0 * e0 + e1 * e1 + e2 * e2 + e3 * e3;
        }
        out[1 + QELEMS + n] = (float)bi;
        sRED[tid] = err;
    }
    __syncthreads();
    #pragma unroll
    for (int s = 128; s > 0; s >>= 1) {
        if (tid < s) sRED[tid] += sRED[tid + s];
        __syncthreads();
    }
    if (tid == 0) g_partial[blockIdx.x] = sRED[0];

    // ---- Deterministic last-block loss finalize ----
    if (tid == 0) {
        __threadfence();
        int old = atomicAdd(&g_ctr, 1);
        sLast = (old == GRID_M - 1) ? 1 : 0;
    }
    __syncthreads();
    if (sLast) {
        sRED[tid] = g_partial[tid];
        __syncthreads();
        #pragma unroll
        for (int s = 128; s > 0; s >>= 1) {
            if (tid < s) sRED[tid] += sRED[tid + s];
            __syncthreads();
        }
        if (tid == 0) {
            out[0] = 1.25f * sRED[0] / (float)QELEMS;   // q_loss + 0.25*e_loss, equal in value
            out[out_size - 1] = 0.0f;                   // n_resurrected
            g_ctr = 0;                                  // reset for next graph replay
        }
    }
}

// ---------------------------------------------------------------------------
extern "C" void kernel_launch(void* const* d_in, const int* in_sizes, int n_in,
                              void* d_out, int out_size) {
    const float* in = (const float*)d_in[0];   // [B, D, T] float32
    const float* w  = (const float*)d_in[1];   // [K, D]    float32
    float* out = (float*)d_out;

    cudaFuncSetAttribute(vq_all_kernel, cudaFuncAttributeMaxDynamicSharedMemorySize, SM_TOTAL);
    vq_all_kernel<<<GRID_M, 256, SM_TOTAL>>>(in, w, out, out_size);
}

// round 9
// speedup vs baseline: 6.4861x; 1.2578x over previous
#include <cuda_runtime.h>
#include <cuda_fp16.h>
#include <cstdint>

// ---------------------------------------------------------------------------
// Problem constants
// ---------------------------------------------------------------------------
#define BB 32
#define DD 64
#define TT 2048
#define KK 1024
#define NN (BB * TT)              // 65536 rows
#define QELEMS (BB * DD * TT)     // 4194304
// Output (float32): [loss(1) | quantized(QELEMS) | indices(NN) | n_resurrected(1)]

#define TILE_M  256               // rows per CTA (32 per warp)
#define CHUNK_N 128               // codewords per staged chunk
#define GRID_M  (NN / TILE_M)     // 256 CTAs
#define NCHUNK  (KK / CHUNK_N)    // 8

#define BS 72                     // sB row stride in halves (144 B)
#define B_BUF_BYTES 18432         // 128 rows x 144 B

// Dynamic smem layout (bytes)
#define SM_X     0                // 256 x 64 floats (xor-swizzled) = 65536
#define SM_B     65536            // 2 x 18432 = 36864 (cp.async ping-pong)
#define SM_CAND  102400           // 256 x 2 ints = 2048
#define SM_RED   104448           // 256 floats   = 1024
#define SM_TOTAL 105472

__device__ __half g_wh[KK * DD];  // normalized codebook, fp16 (pre-kernel)
__device__ float  g_partial[GRID_M];
__device__ int    g_ctr;          // zero-initialized; reset by last block

// m16n8k16 fp16 MMA, fp32 accum, D += A*B
#define MMA_F16(d, a, b0, b1)                                                 \
    asm volatile("mma.sync.aligned.m16n8k16.row.col.f32.f16.f16.f32 "         \
                 "{%0,%1,%2,%3}, {%4,%5,%6,%7}, {%8,%9}, {%0,%1,%2,%3};"      \
                 : "+f"((d)[0]), "+f"((d)[1]), "+f"((d)[2]), "+f"((d)[3])     \
                 : "r"((a)[0]), "r"((a)[1]), "r"((a)[2]), "r"((a)[3]),        \
                   "r"(b0), "r"(b1))

#define LDSM4(r, a)                                                           \
    asm volatile("ldmatrix.sync.aligned.m8n8.x4.shared.b16 {%0,%1,%2,%3}, [%4];" \
                 : "=r"((r)[0]), "=r"((r)[1]), "=r"((r)[2]), "=r"((r)[3])     \
                 : "r"(a))

#define CP_ASYNC_16(dst_u32, src_ptr) \
    asm volatile("cp.async.ca.shared.global [%0], [%1], 16;" \
                 :: "r"(dst_u32), "l"(src_ptr) : "memory")
#define CP_ASYNC_COMMIT() asm volatile("cp.async.commit_group;" ::: "memory")
#define CP_ASYNC_WAIT(n)  asm volatile("cp.async.wait_group %0;" :: "n"(n) : "memory")

__device__ __forceinline__ uint32_t smem_to_u32(const void* p) {
    uint32_t a;
    asm("{ .reg .u64 t; cvta.to.shared.u64 t, %1; cvt.u32.u64 %0, t; }" : "=r"(a) : "l"(p));
    return a;
}
__device__ __forceinline__ uint32_t pack_h2(float a, float b) {
    __half2 h = __floats2half2_rn(a, b);
    return *(uint32_t*)&h;
}
// monotone fp32 -> u32 (unsigned compare order == float order)
__device__ __forceinline__ uint32_t fkey(float v) {
    int s = __float_as_int(v);
    return (uint32_t)(s ^ ((s >> 31) | 0x80000000));
}

// ---------------------------------------------------------------------------
// Pre-kernel: normalize codebook -> fp16 operand (once, not per-CTA)
// ---------------------------------------------------------------------------
__global__ void norm_weight_kernel(const float* __restrict__ w) {
    int row  = blockIdx.x * blockDim.y + threadIdx.y;
    int lane = threadIdx.x;
    float a = w[row * DD + lane];
    float b = w[row * DD + 32 + lane];
    float s = a * a + b * b;
    #pragma unroll
    for (int o = 16; o; o >>= 1) s += __shfl_xor_sync(0xFFFFFFFFu, s, o);
    float inv = 1.0f / fmaxf(sqrtf(s), 1e-12f);
    g_wh[row * DD + lane]      = __float2half_rn(a * inv);
    g_wh[row * DD + 32 + lane] = __float2half_rn(b * inv);
}

// ---------------------------------------------------------------------------
// Main fused kernel
// ---------------------------------------------------------------------------
__global__ __launch_bounds__(256, 2)
void vq_all_kernel(const float* __restrict__ in, const float* __restrict__ w,
                   float* __restrict__ out, int out_size) {
    extern __shared__ char smem[];
    float*    sX    = (float*)(smem + SM_X);
    __half*   sB    = (__half*)(smem + SM_B);
    int*      sCand = (int*)(smem + SM_CAND);
    float*    sRED  = (float*)(smem + SM_RED);
    __shared__ int sLast;

    const int tid  = threadIdx.x;
    const int wid  = tid >> 5;
    const int lane = tid & 31;
    const int g    = lane >> 2;   // groupID (0..7)
    const int tig  = lane & 3;    // thread in group
    const int lr   = lane & 7;    // ldmatrix row
    const int lj   = lane >> 3;   // ldmatrix tile

    const uint32_t sB_u32 = smem_to_u32(sB);

    // ---- Prologue: stage chunk 0 via cp.async (overlaps phase 1) ----
    {
        const char* src = (const char*)g_wh;
        #pragma unroll
        for (int it = 0; it < 4; ++it) {
            int gi  = tid + it * 256;          // [0,1024) 16B units
            int row = gi >> 3;
            int j   = gi & 7;
            CP_ASYNC_16(sB_u32 + (uint32_t)(row * 144 + j * 16), src + gi * 16);
        }
        CP_ASYNC_COMMIT();
    }

    // ---- Phase 1: load + normalize 256 rows into xor-swizzled smem X ----
    {
        int n = blockIdx.x * TILE_M + tid;
        int b = n >> 11;
        int t = n & (TT - 1);
        const float* xp = in + (size_t)b * DD * TT + t;
        float x[DD];
        float ss = 0.0f;
        #pragma unroll
        for (int d = 0; d < DD; ++d) { float v = xp[(size_t)d * TT]; x[d] = v; ss += v * v; }
        float inv = 1.0f / fmaxf(sqrtf(ss), 1e-12f);
        const int sw = tid & 15;
        #pragma unroll
        for (int cd = 0; cd < 16; ++cd) {
            *(float4*)(sX + tid * 64 + ((cd ^ sw) << 2)) =
                make_float4(x[4 * cd] * inv, x[4 * cd + 1] * inv,
                            x[4 * cd + 2] * inv, x[4 * cd + 3] * inv);
        }
    }
    __syncthreads();

    // ---- Resident A fragments (fp16) for this warp's 32 rows (2 groups) ----
    const int rbase = wid * 32;
    uint32_t A[2][4][4];
    #pragma unroll
    for (int grp = 0; grp < 2; ++grp) {
        const int r0 = rbase + grp * 16 + g;
        const int r1 = r0 + 8;
        const int s0 = r0 & 15, s1 = r1 & 15;
        #pragma unroll
        for (int c = 0; c < 4; ++c) {
            const int ch0 = c * 4 + (tig >> 1);        // chunk of k0 = 16c + 2tig
            const int off = (2 * tig) & 3;
            const float* pa  = sX + r0 * 64 + ((ch0 ^ s0) << 2) + off;
            const float* pb  = sX + r1 * 64 + ((ch0 ^ s1) << 2) + off;
            const float* pa8 = sX + r0 * 64 + (((ch0 + 2) ^ s0) << 2) + off;
            const float* pb8 = sX + r1 * 64 + (((ch0 + 2) ^ s1) << 2) + off;
            A[grp][c][0] = pack_h2(pa[0],  pa[1]);
            A[grp][c][1] = pack_h2(pb[0],  pb[1]);
            A[grp][c][2] = pack_h2(pa8[0], pa8[1]);
            A[grp][c][3] = pack_h2(pb8[0], pb8[1]);
        }
    }

    uint32_t k0[4] = {0, 0, 0, 0}, k1[4] = {0, 0, 0, 0};   // packed top-2 keys
    const uint32_t ldsm_base = sB_u32 + (uint32_t)(lr * 144 + lj * 16);

    #pragma unroll 1
    for (int nt = 0; nt < NCHUNK; ++nt) {
        // ---- Stage chunk nt+1 into the other buffer; wait for chunk nt ----
        if (nt < NCHUNK - 1) {
            const char* src = (const char*)(g_wh + (size_t)(nt + 1) * CHUNK_N * DD);
            uint32_t dstb = sB_u32 + (uint32_t)(((nt + 1) & 1) * B_BUF_BYTES);
            #pragma unroll
            for (int it = 0; it < 4; ++it) {
                int gi  = tid + it * 256;
                int row = gi >> 3;
                int j   = gi & 7;
                CP_ASYNC_16(dstb + (uint32_t)(row * 144 + j * 16), src + gi * 16);
            }
            CP_ASYNC_COMMIT();
            CP_ASYNC_WAIT(1);
        } else {
            CP_ASYNC_WAIT(0);
        }
        __syncthreads();

        const uint32_t lbase = ldsm_base + (uint32_t)((nt & 1) * B_BUF_BYTES);

        // ---- 8 sub-tiles of 16 codewords ----
        #pragma unroll
        for (int pp = 0; pp < 8; ++pp) {
            const int n0 = pp * 16;
            uint32_t Bf[4][4];                       // [h*2+seg][tile]
            const uint32_t a0 = lbase + (uint32_t)(n0 * 144);
            LDSM4(Bf[0], a0);                        // h0, k 0..31
            LDSM4(Bf[1], a0 + 64);                   // h0, k 32..63
            LDSM4(Bf[2], a0 + 8 * 144);              // h1, k 0..31
            LDSM4(Bf[3], a0 + 8 * 144 + 64);         // h1, k 32..63

            float acc[2][2][4];
            #pragma unroll
            for (int grp = 0; grp < 2; ++grp)
                #pragma unroll
                for (int h = 0; h < 2; ++h)
                    #pragma unroll
                    for (int e = 0; e < 4; ++e) acc[grp][h][e] = 0.0f;
            #pragma unroll
            for (int c = 0; c < 4; ++c) {
                const int bi_ = c >> 1;
                const int be  = (c & 1) * 2;
                MMA_F16(acc[0][0], A[0][c], Bf[bi_][be],     Bf[bi_][be + 1]);
                MMA_F16(acc[0][1], A[0][c], Bf[2 + bi_][be], Bf[2 + bi_][be + 1]);
                MMA_F16(acc[1][0], A[1][c], Bf[bi_][be],     Bf[bi_][be + 1]);
                MMA_F16(acc[1][1], A[1][c], Bf[2 + bi_][be], Bf[2 + bi_][be + 1]);
            }
            // pair-max -> packed key -> branch-free top-2
            #pragma unroll
            for (int grp = 0; grp < 2; ++grp) {
                #pragma unroll
                for (int h = 0; h < 2; ++h) {
                    const uint32_t code = 1023u - (uint32_t)(nt * 64 + pp * 8 + h * 4 + tig);
                    float vA = fmaxf(acc[grp][h][0], acc[grp][h][1]);
                    float vB = fmaxf(acc[grp][h][2], acc[grp][h][3]);
                    uint32_t kA = (fkey(vA) & 0xFFFFFC00u) | code;
                    uint32_t kB = (fkey(vB) & 0xFFFFFC00u) | code;
                    const int rY = grp * 2, rZ = rY + 1;
                    uint32_t tA = min(k0[rY], kA);
                    k0[rY] = max(k0[rY], kA);
                    k1[rY] = max(k1[rY], tA);
                    uint32_t tB = min(k0[rZ], kB);
                    k0[rZ] = max(k0[rZ], kB);
                    k1[rZ] = max(k1[rZ], tB);
                }
            }
        }
        __syncthreads();   // buf[nt&1] fully consumed before next refill
    }

    // ---- Merge top-2 key sets across the 4 lanes of each group ----
    #pragma unroll
    for (int r = 0; r < 4; ++r) {
        #pragma unroll
        for (int off = 1; off <= 2; off <<= 1) {
            uint32_t o0 = __shfl_xor_sync(0xFFFFFFFFu, k0[r], off);
            uint32_t o1 = __shfl_xor_sync(0xFFFFFFFFu, k1[r], off);
            uint32_t mn = min(k0[r], o0);
            k0[r] = max(k0[r], o0);
            k1[r] = max(max(k1[r], o1), mn);
        }
        if (tig == 0) {
            int row = rbase + (r >> 1) * 16 + (r & 1) * 8 + g;
            sCand[row * 2 + 0] = 1023 - (int)(k0[r] & 1023u);
            sCand[row * 2 + 1] = 1023 - (int)(k1[r] & 1023u);
        }
    }
    __syncthreads();

    // ---- Cooperative exact fp32 rescore; write normalized winner into sX ----
    const float NEGINF = -3.402823466e+38f;
    #pragma unroll 1
    for (int s = 0; s < 4; ++s) {
        const int row = rbase + g * 4 + s;
        const int sw  = row & 15;
        const int p0 = sCand[row * 2], p1 = sCand[row * 2 + 1];
        int cand[4] = {2 * p0, 2 * p0 + 1, 2 * p1, 2 * p1 + 1};
        float4 xq[4];
        #pragma unroll
        for (int j = 0; j < 4; ++j)
            xq[j] = *(const float4*)(sX + row * 64 + (((tig * 4 + j) ^ sw) << 2));
        float best = NEGINF, binv = 1.0f;
        int   bi   = KK;
        #pragma unroll
        for (int c = 0; c < 4; ++c) {
            const int idx = cand[c];
            const float4* wp = (const float4*)(w + (size_t)idx * DD) + tig * 4;
            float dot = 0.0f, ssw = 0.0f;
            #pragma unroll
            for (int j = 0; j < 4; ++j) {
                float4 v = wp[j];
                dot += v.x * xq[j].x + v.y * xq[j].y + v.z * xq[j].z + v.w * xq[j].w;
                ssw += v.x * v.x + v.y * v.y + v.z * v.z + v.w * v.w;
            }
            dot += __shfl_xor_sync(0xFFFFFFFFu, dot, 1);
            ssw += __shfl_xor_sync(0xFFFFFFFFu, ssw, 1);
            dot += __shfl_xor_sync(0xFFFFFFFFu, dot, 2);
            ssw += __shfl_xor_sync(0xFFFFFFFFu, ssw, 2);
            float inv = 1.0f / fmaxf(sqrtf(ssw), 1e-12f);
            float d   = dot * inv;
            if (d > best || (d == best && idx < bi)) { best = d; bi = idx; binv = inv; }
        }
        // overwrite this row of sX with the normalized winner codeword
        {
            const float4* wp = (const float4*)(w + (size_t)bi * DD) + tig * 4;
            #pragma unroll
            for (int j = 0; j < 4; ++j) {
                float4 v = wp[j];
                *(float4*)(sX + row * 64 + (((tig * 4 + j) ^ sw) << 2)) =
                    make_float4(v.x * binv, v.y * binv, v.z * binv, v.w * binv);
            }
        }
        if (tig == 0) {
            sCand[row * 2] = bi;
            sRED[row] = 2.0f - 2.0f * best;   // ||q - x||^2 for unit vectors
        }
    }
    __syncthreads();

    // ---- Winner phase: stream own smem row (now q) to gmem, coalesced ----
    {
        int n = blockIdx.x * TILE_M + tid;
        int b = n >> 11;
        int t = n & (TT - 1);
        const int sw = tid & 15;
        float* qp = out + 1 + (size_t)b * DD * TT + t;
        #pragma unroll
        for (int i = 0; i < 16; ++i) {
            float4 q = *(const float4*)(sX + tid * 64 + ((i ^ sw) << 2));
            qp[(size_t)(i * 4 + 0) * TT] = q.x;
            qp[(size_t)(i * 4 + 1) * TT] = q.y;
            qp[(size_t)(i * 4 + 2) * TT] = q.z;
            qp[(size_t)(i * 4 + 3) * TT] = q.w;
        }
        out[1 + QELEMS + n] = (float)sCand[tid * 2];
    }
    __syncthreads();
    #pragma unroll
    for (int s = 128; s > 0; s >>= 1) {
        if (tid < s) sRED[tid] += sRED[tid + s];
        __syncthreads();
    }
    if (tid == 0) g_partial[blockIdx.x] = sRED[0];

    // ---- Deterministic last-block loss finalize ----
    if (tid == 0) {
        __threadfence();
        int old = atomicAdd(&g_ctr, 1);
        sLast = (old == GRID_M - 1) ? 1 : 0;
    }
    __syncthreads();
    if (sLast) {
        sRED[tid] = g_partial[tid];
        __syncthreads();
        #pragma unroll
        for (int s = 128; s > 0; s >>= 1) {
            if (tid < s) sRED[tid] += sRED[tid + s];
            __syncthreads();
        }
        if (tid == 0) {
            out[0] = 1.25f * sRED[0] / (float)QELEMS;   // q_loss + 0.25*e_loss (equal in value)
            out[out_size - 1] = 0.0f;                   // n_resurrected
            g_ctr = 0;                                  // reset for next graph replay
        }
    }
}

// ---------------------------------------------------------------------------
extern "C" void kernel_launch(void* const* d_in, const int* in_sizes, int n_in,
                              void* d_out, int out_size) {
    const float* in = (const float*)d_in[0];   // [B, D, T] float32
    const float* w  = (const float*)d_in[1];   // [K, D]    float32
    float* out = (float*)d_out;

    cudaFuncSetAttribute(vq_all_kernel, cudaFuncAttributeMaxDynamicSharedMemorySize, SM_TOTAL);

    norm_weight_kernel<<<KK / 8, dim3(32, 8)>>>(w);
    vq_all_kernel<<<GRID_M, 256, SM_TOTAL>>>(in, w, out, out_size);
}